// round 7
// baseline (speedup 1.0000x reference)
#include <cuda_runtime.h>
#include <cuda_bf16.h>
#include <mma.h>
#include <math.h>
#include <stdint.h>

using namespace nvcuda;

typedef unsigned long long ull;
typedef unsigned int uint;

// Problem dims (fixed)
#define NN 2048
#define DD 512
#define HH 256
#define LL 16
#define L2 32

#define OFF_MU (NN * NN)
#define OFF_LV (NN * NN + NN * LL)

#define SLOPE 0.01f
#define AA_C ((1.0f + SLOPE) * 0.5f)
#define BB_C ((1.0f - SLOPE) * 0.5f)

// Scratch (device globals; no allocation allowed)
__device__ __nv_bfloat16 g_Yhi[NN * HH];       // Y = X@W1^T, bf16 split hi [2048,256]
__device__ __nv_bfloat16 g_Ylo[NN * HH];       // bf16 split lo
__device__ float g_Hh[NN * HH];                // leaky(A@Y + b1) fp32 (2MB)
__device__ float g_G[NN * L2];                 // Hh @ [Wmu;Wlv]^T
__device__ float g_MLp[16][NN * L2];           // split-K partials of A @ G
__device__ float g_P[NN * L2];
__device__ float g_Qb[NN * L2];
__device__ float g_S[NN];
__device__ float g_T[NN];

// ---------------------------------------------------------------------------
// f32x2 packed helpers
// ---------------------------------------------------------------------------
__device__ __forceinline__ ull pack2(float x) {
    ull r; asm("mov.b64 %0, {%1, %1};" : "=l"(r) : "f"(x)); return r;
}
__device__ __forceinline__ float2 unpack2(ull v) {
    float2 r; asm("mov.b64 {%0, %1}, %2;" : "=f"(r.x), "=f"(r.y) : "l"(v)); return r;
}
__device__ __forceinline__ void fma2(ull& d, ull a, ull b) {
    asm("fma.rn.f32x2 %0, %1, %2, %0;" : "+l"(d) : "l"(a), "l"(b));
}
__device__ __forceinline__ ull add2(ull a, ull b) {
    ull r; asm("add.rn.f32x2 %0, %1, %2;" : "=l"(r) : "l"(a), "l"(b)); return r;
}

// bf16 split: (x0,x1) -> packed hi pair + packed lo pair (elem0 in low half)
__device__ __forceinline__ void split2(float x0, float x1, uint& hp, uint& lp) {
    asm("cvt.rn.bf16x2.f32 %0, %1, %2;" : "=r"(hp) : "f"(x1), "f"(x0));
    float h0 = __int_as_float(hp << 16);
    float h1 = __int_as_float(hp & 0xFFFF0000u);
    float l0 = x0 - h0, l1 = x1 - h1;
    asm("cvt.rn.bf16x2.f32 %0, %1, %2;" : "=r"(lp) : "f"(l1), "f"(l0));
}

template <bool C, class T, class F> struct cond_t { using type = T; };
template <class T, class F> struct cond_t<false, T, F> { using type = F; };

// ---------------------------------------------------------------------------
// wgemm64: direct-output GEMM, 64x64 tile, NO split-K. 256 threads, 8 warps,
// warp tile 32x16 (2 m-frags x 1 n-frag), BK=32, 3-MMA bf16 split,
// register prefetch of next chunk.
//   BMODE 0 (K1): A=X fp32, B=W1 fp32 [N,K] row-major (col_major frags);
//                 epilogue: bf16-split -> g_Yhi/g_Ylo.
//   BMODE 1 (K2): A=A_hat fp32, B=Y pre-split bf16 [K,N] row-major;
//                 epilogue: + b1, leaky -> g_Hh fp32.
// Grid: (N/64, M/64); consecutive bids share A rows (L2 reuse of A).
// ---------------------------------------------------------------------------
template <int BMODE>
__global__ __launch_bounds__(256) void wgemm64(
    const float* __restrict__ A, int lda,
    const float* __restrict__ Bf, int ldb,
    const __nv_bfloat16* __restrict__ Bhi, const __nv_bfloat16* __restrict__ Blo,
    int K, const float* __restrict__ bias)
{
    __shared__ __nv_bfloat16 sAhi[64 * 40], sAlo[64 * 40];
    __shared__ __nv_bfloat16 sBhi[2560], sBlo[2560];   // mode0: 64x40, mode1: 32x72
    __shared__ float sC[64 * 68];

    const int tid = threadIdx.x;
    const int wid = tid >> 5;
    const int wm = wid & 1;          // 2 m-warp rows of 32
    const int wn = wid >> 1;         // 4 n-warp cols of 16
    const int n0 = blockIdx.x * 64;
    const int m0 = blockIdx.y * 64;

    wmma::fragment<wmma::accumulator, 16, 16, 16, float> acc[2];
    wmma::fill_fragment(acc[0], 0.0f);
    wmma::fill_fragment(acc[1], 0.0f);

    using BLay = typename cond_t<BMODE == 0, wmma::col_major, wmma::row_major>::type;

    // A loader: 64 rows x 32 k; r = tid>>2, two float4 at cb, cb+4
    const int ar = tid >> 2;
    const int acb = (tid & 3) << 3;
    // B mode0 loader: same shape (n-local rows, k cols)
    // B mode1 loader: 32 k-rows x 64 n; r = tid>>3, 8 bf16 at c
    const int b1r = tid >> 3;
    const int b1c = (tid & 7) << 3;

    float4 aR[2], bR[2];
    uint4 bhR, blR;

    auto loadA = [&](int kt) {
        const float* p = &A[(size_t)(m0 + ar) * lda + kt + acb];
        aR[0] = *(const float4*)p;
        aR[1] = *(const float4*)(p + 4);
    };
    auto loadB = [&](int kt) {
        if (BMODE == 0) {
            const float* p = &Bf[(size_t)(n0 + ar) * ldb + kt + acb];
            bR[0] = *(const float4*)p;
            bR[1] = *(const float4*)(p + 4);
        } else {
            size_t gb = (size_t)(kt + b1r) * ldb + n0 + b1c;
            bhR = *(const uint4*)&Bhi[gb];
            blR = *(const uint4*)&Blo[gb];
        }
    };

    loadA(0);
    loadB(0);

    for (int kt = 0; kt < K; kt += 32) {
        // stage A
        {
            uint h01, l01, h23, l23;
            split2(aR[0].x, aR[0].y, h01, l01);
            split2(aR[0].z, aR[0].w, h23, l23);
            *(uint2*)&sAhi[ar * 40 + acb] = make_uint2(h01, h23);
            *(uint2*)&sAlo[ar * 40 + acb] = make_uint2(l01, l23);
            split2(aR[1].x, aR[1].y, h01, l01);
            split2(aR[1].z, aR[1].w, h23, l23);
            *(uint2*)&sAhi[ar * 40 + acb + 4] = make_uint2(h01, h23);
            *(uint2*)&sAlo[ar * 40 + acb + 4] = make_uint2(l01, l23);
        }
        // stage B
        if (BMODE == 0) {
            uint h01, l01, h23, l23;
            split2(bR[0].x, bR[0].y, h01, l01);
            split2(bR[0].z, bR[0].w, h23, l23);
            *(uint2*)&sBhi[ar * 40 + acb] = make_uint2(h01, h23);
            *(uint2*)&sBlo[ar * 40 + acb] = make_uint2(l01, l23);
            split2(bR[1].x, bR[1].y, h01, l01);
            split2(bR[1].z, bR[1].w, h23, l23);
            *(uint2*)&sBhi[ar * 40 + acb + 4] = make_uint2(h01, h23);
            *(uint2*)&sBlo[ar * 40 + acb + 4] = make_uint2(l01, l23);
        } else {
            *(uint4*)&sBhi[b1r * 72 + b1c] = bhR;
            *(uint4*)&sBlo[b1r * 72 + b1c] = blR;
        }
        __syncthreads();

        // prefetch next chunk while MMA runs
        if (kt + 32 < K) {
            loadA(kt + 32);
            loadB(kt + 32);
        }

        #pragma unroll
        for (int ks = 0; ks < 2; ks++) {
            wmma::fragment<wmma::matrix_a, 16, 16, 16, __nv_bfloat16, wmma::row_major> ah[2], al[2];
            wmma::fragment<wmma::matrix_b, 16, 16, 16, __nv_bfloat16, BLay> bh, bl;
            #pragma unroll
            for (int i = 0; i < 2; i++) {
                int row = wm * 32 + i * 16;
                wmma::load_matrix_sync(ah[i], &sAhi[row * 40 + ks * 16], 40);
                wmma::load_matrix_sync(al[i], &sAlo[row * 40 + ks * 16], 40);
            }
            if (BMODE == 0) {
                wmma::load_matrix_sync(bh, &sBhi[(wn * 16) * 40 + ks * 16], 40);
                wmma::load_matrix_sync(bl, &sBlo[(wn * 16) * 40 + ks * 16], 40);
            } else {
                wmma::load_matrix_sync(bh, &sBhi[(ks * 16) * 72 + wn * 16], 72);
                wmma::load_matrix_sync(bl, &sBlo[(ks * 16) * 72 + wn * 16], 72);
            }
            #pragma unroll
            for (int i = 0; i < 2; i++) {
                wmma::mma_sync(acc[i], ah[i], bh, acc[i]);
                wmma::mma_sync(acc[i], ah[i], bl, acc[i]);
                wmma::mma_sync(acc[i], al[i], bh, acc[i]);
            }
        }
        __syncthreads();
    }

    // Epilogue via smem staging
    #pragma unroll
    for (int i = 0; i < 2; i++)
        wmma::store_matrix_sync(&sC[(wm * 32 + i * 16) * 68 + wn * 16], acc[i],
                                68, wmma::mem_row_major);
    __syncthreads();

    const int er = tid >> 2;          // 0..63
    const int ec = (tid & 3) << 4;    // 0, 16, 32, 48
    #pragma unroll
    for (int q = 0; q < 4; q++) {
        float4 v = *(const float4*)&sC[er * 68 + ec + q * 4];
        size_t gi = (size_t)(m0 + er) * HH + n0 + ec + q * 4;
        if (BMODE == 0) {
            uint h01, l01, h23, l23;
            split2(v.x, v.y, h01, l01);
            split2(v.z, v.w, h23, l23);
            *(uint2*)&g_Yhi[gi] = make_uint2(h01, h23);
            *(uint2*)&g_Ylo[gi] = make_uint2(l01, l23);
        } else {
            float4 bb = *(const float4*)&bias[n0 + ec + q * 4];
            float a = v.x + bb.x, b = v.y + bb.y, c = v.z + bb.z, d = v.w + bb.w;
            *(float4*)&g_Hh[gi] = make_float4(
                fmaxf(a, SLOPE * a), fmaxf(b, SLOPE * b),
                fmaxf(c, SLOPE * c), fmaxf(d, SLOPE * d));
        }
    }
}

// ---------------------------------------------------------------------------
// K3b: G[n, c] = sum_k Hh[n,k] * Wcat[c,k]; warp-per-row, 8 rows/block.
// ---------------------------------------------------------------------------
__global__ __launch_bounds__(256) void k3b_gmat(
    const float* __restrict__ Wmu, const float* __restrict__ Wlv)
{
    __shared__ float Ws[32][260];
    const int tid = threadIdx.x;
    const int m0 = blockIdx.x * 8;

    #pragma unroll
    for (int it = 0; it < 8; it++) {
        int idx = tid + it * 256;
        int c = idx >> 6, k4 = (idx & 63) << 2;
        const float* src = (c < 16) ? &Wmu[c * 256 + k4] : &Wlv[(c - 16) * 256 + k4];
        *(float4*)&Ws[c][k4] = *(const float4*)src;
    }
    __syncthreads();

    const int w = tid >> 5;
    const int c = tid & 31;
    const float4* hr = (const float4*)&g_Hh[(size_t)(m0 + w) * 256];
    float acc = 0.f;
    #pragma unroll 8
    for (int k4 = 0; k4 < 64; k4++) {
        float4 h = hr[k4];
        float4 ww = *(const float4*)&Ws[c][k4 * 4];
        acc = fmaf(h.x, ww.x, acc);
        acc = fmaf(h.y, ww.y, acc);
        acc = fmaf(h.z, ww.z, acc);
        acc = fmaf(h.w, ww.w, acc);
    }
    g_G[(m0 + w) * 32 + c] = acc;
}

// ---------------------------------------------------------------------------
// K4: split-K (16) A @ G. Tile 256 x 32, BK=16, micro 8x4 via f32x2.
// ---------------------------------------------------------------------------
__global__ __launch_bounds__(256) void k4_ag(const float* __restrict__ A)
{
    __shared__ float As[16][260];
    __shared__ float Bs[16][36];

    const int tid = threadIdx.x;
    const int m0 = blockIdx.x * 256;
    const int k0 = blockIdx.y * 128;

    const int ar = tid >> 2;
    const int ac = (tid & 3) << 2;
    const float* Ap = A + (size_t)(m0 + ar) * NN + k0 + ac;

    const int tx = tid & 7;
    const int ty = tid >> 3;

    ull acc[8][2];
    #pragma unroll
    for (int u = 0; u < 8; u++) { acc[u][0] = 0ull; acc[u][1] = 0ull; }

    for (int kt = 0; kt < 128; kt += 16) {
        #pragma unroll
        for (int j = 0; j < 4; j++) {
            float4 a4 = *(const float4*)(Ap + (size_t)(64 * j) * NN + kt);
            As[ac + 0][ar + 64 * j] = a4.x; As[ac + 1][ar + 64 * j] = a4.y;
            As[ac + 2][ar + 64 * j] = a4.z; As[ac + 3][ar + 64 * j] = a4.w;
        }
        if (tid < 128) {
            int brr = tid >> 3, bcc = (tid & 7) << 2;
            *(float4*)&Bs[brr][bcc] =
                *(const float4*)&g_G[(size_t)(k0 + kt + brr) * 32 + bcc];
        }
        __syncthreads();

        #pragma unroll
        for (int kk = 0; kk < 16; kk++) {
            float4 av0 = *(const float4*)&As[kk][ty * 4];
            float4 av1 = *(const float4*)&As[kk][128 + ty * 4];
            ulonglong2 bv = *(const ulonglong2*)&Bs[kk][tx * 4];
            ull pa[8];
            pa[0] = pack2(av0.x); pa[1] = pack2(av0.y);
            pa[2] = pack2(av0.z); pa[3] = pack2(av0.w);
            pa[4] = pack2(av1.x); pa[5] = pack2(av1.y);
            pa[6] = pack2(av1.z); pa[7] = pack2(av1.w);
            #pragma unroll
            for (int u = 0; u < 8; u++) {
                fma2(acc[u][0], pa[u], bv.x);
                fma2(acc[u][1], pa[u], bv.y);
            }
        }
        __syncthreads();
    }

    float* outp = g_MLp[blockIdx.y];
    #pragma unroll
    for (int u = 0; u < 8; u++) {
        int row = m0 + ((u < 4) ? (ty * 4 + u) : (128 + ty * 4 + u - 4));
        float2 c0 = unpack2(acc[u][0]);
        float2 c1 = unpack2(acc[u][1]);
        *(float4*)&outp[(size_t)row * 32 + tx * 4] =
            make_float4(c0.x, c0.y, c1.x, c1.y);
    }
}

// ---------------------------------------------------------------------------
// K5: reduce 16 partials, biases, mu/logvar, reparameterize, P/Qb, S/T.
// ---------------------------------------------------------------------------
__global__ __launch_bounds__(256) void k5_epi(
    const float* __restrict__ eps, const float* __restrict__ bmu,
    const float* __restrict__ blv, const float* __restrict__ Wd1,
    const float* __restrict__ bd1, const float* __restrict__ Wd2,
    const float* __restrict__ bd2, float* __restrict__ out)
{
    __shared__ float mls[8][32];
    __shared__ float zs[8][16];
    const int r = threadIdx.x >> 5;
    const int c = threadIdx.x & 31;
    const int n = blockIdx.x * 8 + r;
    const size_t o = (size_t)n * 32 + c;

    float v = 0.f;
    #pragma unroll
    for (int s = 0; s < 16; s++) v += g_MLp[s][o];

    if (c < 16) {
        v += bmu[c];
        out[OFF_MU + n * 16 + c] = v;
    } else {
        v += blv[c - 16];
        out[OFF_LV + n * 16 + (c - 16)] = v;
    }
    mls[r][c] = v;
    __syncthreads();

    if (c < 16) {
        float z = mls[r][c] + eps[n * 16 + c] * expf(0.5f * mls[r][16 + c]);
        zs[r][c] = z;
    }
    __syncthreads();

    float p = 0.f, q = 0.f;
    #pragma unroll
    for (int l = 0; l < 16; l++) {
        float z = zs[r][l];
        p = fmaf(z, Wd1[c * 32 + l], p);
        q = fmaf(z, Wd1[c * 32 + 16 + l], q);
    }
    float qb = q + bd1[c];
    g_P[o] = p;
    g_Qb[o] = qb;

    float w = Wd2[c];
    float sv = w * p;
    float tv = w * qb;
    #pragma unroll
    for (int off = 16; off >= 1; off >>= 1) {
        sv += __shfl_xor_sync(0xffffffffu, sv, off);
        tv += __shfl_xor_sync(0xffffffffu, tv, off);
    }
    if (c == 0) {
        g_S[n] = AA_C * sv;
        g_T[n] = AA_C * tv + bd2[0];
    }
}

// ---------------------------------------------------------------------------
// Software sigmoid (no MUFU)
// ---------------------------------------------------------------------------
__device__ __forceinline__ float fast_sigmoid(float x)
{
    float ax = fminf(fabsf(x), 30.0f);
    float t = ax * -1.4426950408889634f;
    float tr = t + 12582912.0f;
    int ki = __float_as_int(tr) - 0x4B400000;
    float f = t - (tr - 12582912.0f);
    float p = 1.3333558e-3f;
    p = fmaf(p, f, 9.6181291e-3f);
    p = fmaf(p, f, 5.5504109e-2f);
    p = fmaf(p, f, 2.4022651e-1f);
    p = fmaf(p, f, 6.9314718e-1f);
    p = fmaf(p, f, 1.0f);
    float rr = p * __int_as_float((ki + 127) << 23);
    float d = 1.0f + rr;
    float y = __int_as_float(0x7EF311C3 - __float_as_int(d));
    y = y * (2.0f - d * y);
    y = y * (2.0f - d * y);
    y = y * (2.0f - d * y);
    return (x >= 0.0f) ? y : rr * y;
}

// ---------------------------------------------------------------------------
// K6: decoder via leaky split: logit = S_i + T_j + sum_h (BB*w_h)*|P_ih+Qb_jh|
// P pre-packed in smem as duplicated f32x2 (kills per-h MOV pairs on ALU pipe).
// ---------------------------------------------------------------------------
__global__ __launch_bounds__(256) void k6_decoder(
    float* __restrict__ out, const float* __restrict__ Wd2)
{
    __shared__ ull Ptd[32][66];    // [h][i] duplicated pairs
    __shared__ float Qt[32][68];   // [h][j]
    __shared__ ull ws2s[32];
    __shared__ float Ss[64];
    __shared__ float Ts[64];

    const int tid = threadIdx.x;
    const int i0 = blockIdx.y * 64;
    const int j0 = blockIdx.x * 64;

    #pragma unroll
    for (int t = tid; t < 512; t += 256) {
        int r = t >> 3, c4 = (t & 7) << 2;
        float4 pv = *(const float4*)&g_P[(size_t)(i0 + r) * 32 + c4];
        Ptd[c4 + 0][r] = pack2(pv.x); Ptd[c4 + 1][r] = pack2(pv.y);
        Ptd[c4 + 2][r] = pack2(pv.z); Ptd[c4 + 3][r] = pack2(pv.w);
        float4 qv = *(const float4*)&g_Qb[(size_t)(j0 + r) * 32 + c4];
        Qt[c4 + 0][r] = qv.x; Qt[c4 + 1][r] = qv.y;
        Qt[c4 + 2][r] = qv.z; Qt[c4 + 3][r] = qv.w;
    }
    if (tid < 32) ws2s[tid] = pack2(BB_C * Wd2[tid]);
    if (tid < 64) { Ss[tid] = g_S[i0 + tid]; Ts[tid] = g_T[j0 + tid]; }
    __syncthreads();

    const int tx = tid & 15;
    const int ty = tid >> 4;

    ull acc[4][2];
    #pragma unroll
    for (int u = 0; u < 4; u++) { acc[u][0] = 0ull; acc[u][1] = 0ull; }

    const ull AMASK = 0x7FFFFFFF7FFFFFFFull;
    #pragma unroll
    for (int h = 0; h < 32; h++) {
        ulonglong2 qv = *(const ulonglong2*)&Qt[h][tx * 4];
        ull w2 = ws2s[h];
        const ull* pr = &Ptd[h][ty * 4];
        #pragma unroll
        for (int u = 0; u < 4; u++) {
            ull pd = pr[u];
            ull t0 = add2(pd, qv.x) & AMASK;
            ull t1 = add2(pd, qv.y) & AMASK;
            fma2(acc[u][0], t0, w2);
            fma2(acc[u][1], t1, w2);
        }
    }

    #pragma unroll
    for (int u = 0; u < 4; u++) {
        int i = i0 + ty * 4 + u;
        float si = Ss[ty * 4 + u];
        float2 c0 = unpack2(acc[u][0]);
        float2 c1 = unpack2(acc[u][1]);
        float4 o4;
        o4.x = fast_sigmoid(c0.x + si + Ts[tx * 4 + 0]);
        o4.y = fast_sigmoid(c0.y + si + Ts[tx * 4 + 1]);
        o4.z = fast_sigmoid(c1.x + si + Ts[tx * 4 + 2]);
        o4.w = fast_sigmoid(c1.y + si + Ts[tx * 4 + 3]);
        *(float4*)&out[(size_t)i * NN + j0 + tx * 4] = o4;
    }
}

// ---------------------------------------------------------------------------
extern "C" void kernel_launch(void* const* d_in, const int* in_sizes, int n_in,
                              void* d_out, int out_size)
{
    const float* A_hat = (const float*)d_in[0];
    const float* X     = (const float*)d_in[1];
    const float* eps   = (const float*)d_in[2];
    const float* W1    = (const float*)d_in[3];
    const float* b1    = (const float*)d_in[4];
    const float* Wmu   = (const float*)d_in[5];
    const float* bmu   = (const float*)d_in[6];
    const float* Wlv   = (const float*)d_in[7];
    const float* blv   = (const float*)d_in[8];
    const float* Wd1   = (const float*)d_in[9];
    const float* bd1   = (const float*)d_in[10];
    const float* Wd2   = (const float*)d_in[11];
    const float* bd2   = (const float*)d_in[12];
    float* out = (float*)d_out;

    __nv_bfloat16* Yhi = nullptr; cudaGetSymbolAddress((void**)&Yhi, g_Yhi);
    __nv_bfloat16* Ylo = nullptr; cudaGetSymbolAddress((void**)&Ylo, g_Ylo);

    // K1: Y(hi/lo) = X @ W1^T  (direct, fused bf16-split epilogue)
    wgemm64<0><<<dim3(HH / 64, NN / 64), 256>>>(
        X, DD, W1, DD, nullptr, nullptr, DD, nullptr);
    // K2: Hh = leaky(A_hat @ Y + b1)  (direct, fused epilogue)
    wgemm64<1><<<dim3(HH / 64, NN / 64), 256>>>(
        A_hat, NN, nullptr, HH, Yhi, Ylo, NN, b1);
    // K3b: G = Hh @ [Wmu;Wlv]^T
    k3b_gmat<<<NN / 8, 256>>>(Wmu, Wlv);
    // K4: MLp = A_hat @ G  (split-K 16)
    k4_ag<<<dim3(NN / 256, 16), 256>>>(A_hat);
    // K5: reduce + biases + mu/logvar + Z + P/Qb + S/T
    k5_epi<<<NN / 8, 256>>>(eps, bmu, blv, Wd1, bd1, Wd2, bd2, out);
    // K6: pairwise decoder
    k6_decoder<<<dim3(NN / 64, NN / 64), 256>>>(out, Wd2);
}

// round 10
// speedup vs baseline: 1.2285x; 1.2285x over previous
#include <cuda_runtime.h>
#include <cuda_bf16.h>
#include <mma.h>
#include <math.h>
#include <stdint.h>

using namespace nvcuda;

typedef unsigned long long ull;
typedef unsigned int uint;

// Problem dims (fixed)
#define NN 2048
#define DD 512
#define HH 256
#define LL 16
#define L2 32

#define OFF_MU (NN * NN)
#define OFF_LV (NN * NN + NN * LL)

#define SLOPE 0.01f
#define AA_C ((1.0f + SLOPE) * 0.5f)
#define BB_C ((1.0f - SLOPE) * 0.5f)

// Scratch (device globals; no allocation allowed)
__device__ float g_part[4 * NN * HH];          // split-K fp32 partials (8MB)
__device__ __nv_bfloat16 g_Yhi[NN * HH];       // Y = X@W1^T, bf16 split hi
__device__ __nv_bfloat16 g_Ylo[NN * HH];       // bf16 split lo
__device__ float g_Hh[NN * HH];                // leaky(A@Y + b1) fp32 (2MB)
__device__ float g_G[NN * L2];                 // Hh @ [Wmu;Wlv]^T
__device__ float g_MLp[16][NN * L2];           // split-K partials of A @ G
__device__ float g_P[NN * L2];
__device__ float g_Qb[NN * L2];
__device__ float g_S[NN];
__device__ float g_T[NN];

// ---------------------------------------------------------------------------
// f32x2 packed helpers
// ---------------------------------------------------------------------------
__device__ __forceinline__ ull pack2(float x) {
    ull r; asm("mov.b64 %0, {%1, %1};" : "=l"(r) : "f"(x)); return r;
}
__device__ __forceinline__ float2 unpack2(ull v) {
    float2 r; asm("mov.b64 {%0, %1}, %2;" : "=f"(r.x), "=f"(r.y) : "l"(v)); return r;
}
__device__ __forceinline__ void fma2(ull& d, ull a, ull b) {
    asm("fma.rn.f32x2 %0, %1, %2, %0;" : "+l"(d) : "l"(a), "l"(b));
}
__device__ __forceinline__ ull add2(ull a, ull b) {
    ull r; asm("add.rn.f32x2 %0, %1, %2;" : "=l"(r) : "l"(a), "l"(b)); return r;
}

// bf16 split: (x0,x1) -> packed hi pair + packed lo pair (elem0 in low half)
__device__ __forceinline__ void split2(float x0, float x1, uint& hp, uint& lp) {
    asm("cvt.rn.bf16x2.f32 %0, %1, %2;" : "=r"(hp) : "f"(x1), "f"(x0));
    float h0 = __int_as_float(hp << 16);
    float h1 = __int_as_float(hp & 0xFFFF0000u);
    float l0 = x0 - h0, l1 = x1 - h1;
    asm("cvt.rn.bf16x2.f32 %0, %1, %2;" : "=r"(lp) : "f"(l1), "f"(l0));
}

template <bool C, class T, class F> struct cond_t { using type = T; };
template <class T, class F> struct cond_t<false, T, F> { using type = F; };

// ---------------------------------------------------------------------------
// wgemm: C_part[z] = A[M,K](fp32, split in-kernel) @ B
//   BMODE 0: B = fp32 [N,K] row-major (col_major fragments)  [K1]
//   BMODE 1: B = bf16 hi/lo [K,N] row-major (row_major frags) [K2]
// Block tile 128x128, 8 warps (warp tile 32x64), K-chunk 32, 3-MMA bf16 split.
// Register prefetch of next chunk's global loads overlaps DRAM with MMA.
// ---------------------------------------------------------------------------
template <int BMODE>
__global__ __launch_bounds__(256) void wgemm(
    const float* __restrict__ A, int lda,
    const float* __restrict__ Bf, int ldb,
    const __nv_bfloat16* __restrict__ Bhi, const __nv_bfloat16* __restrict__ Blo,
    int kslice, float* __restrict__ Cpart)
{
    __shared__ __nv_bfloat16 sAhi[128 * 40], sAlo[128 * 40];
    __shared__ __nv_bfloat16 sBhi[128 * 40], sBlo[128 * 40]; // mode1 uses [32][136]

    const int tid = threadIdx.x;
    const int wid = tid >> 5;
    const int wm = wid & 3;
    const int wn = wid >> 2;
    const int m0 = blockIdx.y * 128;
    const int n0 = blockIdx.x * 128;
    const int k0 = blockIdx.z * kslice;

    wmma::fragment<wmma::accumulator, 16, 16, 16, float> acc[2][4];
    #pragma unroll
    for (int i = 0; i < 2; i++)
        #pragma unroll
        for (int j = 0; j < 4; j++) wmma::fill_fragment(acc[i][j], 0.0f);

    using BLay = typename cond_t<BMODE == 0, wmma::col_major, wmma::row_major>::type;

    const int arow = tid >> 3;
    const int acol = (tid & 7) << 2;
    const int b0row = tid >> 3;
    const int b0col = (tid & 7) << 2;
    const int b1row = tid >> 4;
    const int b1col = (tid & 15) << 3;

    float4 aR[4];
    float4 bR[4];
    uint4 bhR[2], blR[2];

    auto loadA = [&](int kt) {
        #pragma unroll
        for (int it = 0; it < 4; it++)
            aR[it] = *(const float4*)&A[(size_t)(m0 + it * 32 + arow) * lda + k0 + kt + acol];
    };
    auto loadB = [&](int kt) {
        if (BMODE == 0) {
            #pragma unroll
            for (int it = 0; it < 4; it++)
                bR[it] = *(const float4*)&Bf[(size_t)(n0 + it * 32 + b0row) * ldb + k0 + kt + b0col];
        } else {
            #pragma unroll
            for (int it = 0; it < 2; it++) {
                size_t gb = (size_t)(k0 + kt + it * 16 + b1row) * HH + n0 + b1col;
                bhR[it] = *(const uint4*)&Bhi[gb];
                blR[it] = *(const uint4*)&Blo[gb];
            }
        }
    };

    loadA(0);
    loadB(0);

    for (int kt = 0; kt < kslice; kt += 32) {
        #pragma unroll
        for (int it = 0; it < 4; it++) {
            int r = it * 32 + arow;
            uint h01, l01, h23, l23;
            split2(aR[it].x, aR[it].y, h01, l01);
            split2(aR[it].z, aR[it].w, h23, l23);
            *(uint2*)&sAhi[r * 40 + acol] = make_uint2(h01, h23);
            *(uint2*)&sAlo[r * 40 + acol] = make_uint2(l01, l23);
        }
        if (BMODE == 0) {
            #pragma unroll
            for (int it = 0; it < 4; it++) {
                int r = it * 32 + b0row;
                uint h01, l01, h23, l23;
                split2(bR[it].x, bR[it].y, h01, l01);
                split2(bR[it].z, bR[it].w, h23, l23);
                *(uint2*)&sBhi[r * 40 + b0col] = make_uint2(h01, h23);
                *(uint2*)&sBlo[r * 40 + b0col] = make_uint2(l01, l23);
            }
        } else {
            #pragma unroll
            for (int it = 0; it < 2; it++) {
                int r = it * 16 + b1row;
                *(uint4*)&sBhi[r * 136 + b1col] = bhR[it];
                *(uint4*)&sBlo[r * 136 + b1col] = blR[it];
            }
        }
        __syncthreads();

        if (kt + 32 < kslice) {
            loadA(kt + 32);
            loadB(kt + 32);
        }

        #pragma unroll
        for (int ks = 0; ks < 2; ks++) {
            wmma::fragment<wmma::matrix_a, 16, 16, 16, __nv_bfloat16, wmma::row_major> ah[2], al[2];
            wmma::fragment<wmma::matrix_b, 16, 16, 16, __nv_bfloat16, BLay> bh[4], bl[4];
            #pragma unroll
            for (int i = 0; i < 2; i++) {
                int row = wm * 32 + i * 16;
                wmma::load_matrix_sync(ah[i], &sAhi[row * 40 + ks * 16], 40);
                wmma::load_matrix_sync(al[i], &sAlo[row * 40 + ks * 16], 40);
            }
            #pragma unroll
            for (int j = 0; j < 4; j++) {
                int col = wn * 64 + j * 16;
                if (BMODE == 0) {
                    wmma::load_matrix_sync(bh[j], &sBhi[col * 40 + ks * 16], 40);
                    wmma::load_matrix_sync(bl[j], &sBlo[col * 40 + ks * 16], 40);
                } else {
                    wmma::load_matrix_sync(bh[j], &sBhi[(ks * 16) * 136 + col], 136);
                    wmma::load_matrix_sync(bl[j], &sBlo[(ks * 16) * 136 + col], 136);
                }
            }
            #pragma unroll
            for (int i = 0; i < 2; i++)
                #pragma unroll
                for (int j = 0; j < 4; j++) {
                    wmma::mma_sync(acc[i][j], ah[i], bh[j], acc[i][j]);
                    wmma::mma_sync(acc[i][j], ah[i], bl[j], acc[i][j]);
                    wmma::mma_sync(acc[i][j], al[i], bh[j], acc[i][j]);
                }
        }
        __syncthreads();
    }

    float* Cz = Cpart + (size_t)blockIdx.z * NN * HH;
    #pragma unroll
    for (int i = 0; i < 2; i++)
        #pragma unroll
        for (int j = 0; j < 4; j++) {
            float* dst = Cz + (size_t)(m0 + wm * 32 + i * 16) * HH + n0 + wn * 64 + j * 16;
            wmma::store_matrix_sync(dst, acc[i][j], HH, wmma::mem_row_major);
        }
}

// ---------------------------------------------------------------------------
// reduce_split: Y = sum of 4 partials, emitted as bf16 hi/lo pair arrays.
// ---------------------------------------------------------------------------
__global__ __launch_bounds__(256) void reduce_split(const float* __restrict__ part)
{
    const size_t S = (size_t)NN * HH;
    size_t i = ((size_t)blockIdx.x * 256 + threadIdx.x) * 4;
    float4 v0 = *(const float4*)&part[i];
    float4 v1 = *(const float4*)&part[S + i];
    float4 v2 = *(const float4*)&part[2 * S + i];
    float4 v3 = *(const float4*)&part[3 * S + i];
    float a = v0.x + v1.x + v2.x + v3.x;
    float b = v0.y + v1.y + v2.y + v3.y;
    float c = v0.z + v1.z + v2.z + v3.z;
    float d = v0.w + v1.w + v2.w + v3.w;
    uint h01, l01, h23, l23;
    split2(a, b, h01, l01);
    split2(c, d, h23, l23);
    *(uint2*)&g_Yhi[i] = make_uint2(h01, h23);
    *(uint2*)&g_Ylo[i] = make_uint2(l01, l23);
}

// ---------------------------------------------------------------------------
// K3a: streaming reduce 4 partials + bias + leaky -> Hh fp32.
// ---------------------------------------------------------------------------
__global__ __launch_bounds__(256) void k3a_hh(const float* __restrict__ b1)
{
    const size_t S = (size_t)NN * HH;
    size_t i = ((size_t)blockIdx.x * 256 + threadIdx.x) * 4;
    int col = (int)(i & (HH - 1));
    float4 v0 = *(const float4*)&g_part[i];
    float4 v1 = *(const float4*)&g_part[S + i];
    float4 v2 = *(const float4*)&g_part[2 * S + i];
    float4 v3 = *(const float4*)&g_part[3 * S + i];
    float4 bb = *(const float4*)&b1[col];
    float a = v0.x + v1.x + v2.x + v3.x + bb.x;
    float b = v0.y + v1.y + v2.y + v3.y + bb.y;
    float c = v0.z + v1.z + v2.z + v3.z + bb.z;
    float d = v0.w + v1.w + v2.w + v3.w + bb.w;
    *(float4*)&g_Hh[i] = make_float4(fmaxf(a, SLOPE * a), fmaxf(b, SLOPE * b),
                                     fmaxf(c, SLOPE * c), fmaxf(d, SLOPE * d));
}

// ---------------------------------------------------------------------------
// K3b: G[n, c] = sum_k Hh[n,k] * Wcat[c,k]; warp-per-row, 8 rows/block.
// ---------------------------------------------------------------------------
__global__ __launch_bounds__(256) void k3b_gmat(
    const float* __restrict__ Wmu, const float* __restrict__ Wlv)
{
    __shared__ float Ws[32][260];
    const int tid = threadIdx.x;
    const int m0 = blockIdx.x * 8;

    #pragma unroll
    for (int it = 0; it < 8; it++) {
        int idx = tid + it * 256;
        int c = idx >> 6, k4 = (idx & 63) << 2;
        const float* src = (c < 16) ? &Wmu[c * 256 + k4] : &Wlv[(c - 16) * 256 + k4];
        *(float4*)&Ws[c][k4] = *(const float4*)src;
    }
    __syncthreads();

    const int w = tid >> 5;
    const int c = tid & 31;
    const float4* hr = (const float4*)&g_Hh[(size_t)(m0 + w) * 256];
    float acc = 0.f;
    #pragma unroll 8
    for (int k4 = 0; k4 < 64; k4++) {
        float4 h = hr[k4];
        float4 ww = *(const float4*)&Ws[c][k4 * 4];
        acc = fmaf(h.x, ww.x, acc);
        acc = fmaf(h.y, ww.y, acc);
        acc = fmaf(h.z, ww.z, acc);
        acc = fmaf(h.w, ww.w, acc);
    }
    g_G[(m0 + w) * 32 + c] = acc;
}

// ---------------------------------------------------------------------------
// K4: split-K (16) A @ G. Tile 64 rows x 32 cols, BK=16, 512 blocks for
// memory-level parallelism (A read is the DRAM floor; occupancy was 12.7%).
// Each thread: 2 rows x 4 cols via f32x2.
// ---------------------------------------------------------------------------
__global__ __launch_bounds__(256) void k4_ag(const float* __restrict__ A)
{
    __shared__ float As[16][68];
    __shared__ float Bs[16][36];

    const int tid = threadIdx.x;
    const int m0 = blockIdx.x * 64;
    const int k0 = blockIdx.y * 128;

    const int ar = tid >> 2;            // 0..63
    const int ac = (tid & 3) << 2;
    const float* Ap = A + (size_t)(m0 + ar) * NN + k0 + ac;

    const int tx = tid & 7;             // col quad (2 f32x2)
    const int ty = tid >> 3;            // 0..31 -> rows ty, ty+32

    ull acc[2][2];
    acc[0][0] = 0ull; acc[0][1] = 0ull; acc[1][0] = 0ull; acc[1][1] = 0ull;

    float4 a4 = *(const float4*)Ap;

    for (int kt = 0; kt < 128; kt += 16) {
        As[ac + 0][ar] = a4.x; As[ac + 1][ar] = a4.y;
        As[ac + 2][ar] = a4.z; As[ac + 3][ar] = a4.w;
        if (tid < 128) {
            int brr = tid >> 3, bcc = (tid & 7) << 2;
            *(float4*)&Bs[brr][bcc] =
                *(const float4*)&g_G[(size_t)(k0 + kt + brr) * 32 + bcc];
        }
        __syncthreads();

        if (kt + 16 < 128) a4 = *(const float4*)(Ap + kt + 16);

        #pragma unroll
        for (int kk = 0; kk < 16; kk++) {
            ull a0 = pack2(As[kk][ty]);
            ull a1 = pack2(As[kk][32 + ty]);
            ulonglong2 bv = *(const ulonglong2*)&Bs[kk][tx * 4];
            fma2(acc[0][0], a0, bv.x);
            fma2(acc[0][1], a0, bv.y);
            fma2(acc[1][0], a1, bv.x);
            fma2(acc[1][1], a1, bv.y);
        }
        __syncthreads();
    }

    float* outp = g_MLp[blockIdx.y];
    #pragma unroll
    for (int u = 0; u < 2; u++) {
        int row = m0 + ty + 32 * u;
        float2 c0 = unpack2(acc[u][0]);
        float2 c1 = unpack2(acc[u][1]);
        *(float4*)&outp[(size_t)row * 32 + tx * 4] =
            make_float4(c0.x, c0.y, c1.x, c1.y);
    }
}

// ---------------------------------------------------------------------------
// K5: reduce 16 partials, biases, mu/logvar, reparameterize, P/Qb, S/T.
// ---------------------------------------------------------------------------
__global__ __launch_bounds__(256) void k5_epi(
    const float* __restrict__ eps, const float* __restrict__ bmu,
    const float* __restrict__ blv, const float* __restrict__ Wd1,
    const float* __restrict__ bd1, const float* __restrict__ Wd2,
    const float* __restrict__ bd2, float* __restrict__ out)
{
    __shared__ float mls[8][32];
    __shared__ float zs[8][16];
    const int r = threadIdx.x >> 5;
    const int c = threadIdx.x & 31;
    const int n = blockIdx.x * 8 + r;
    const size_t o = (size_t)n * 32 + c;

    float v = 0.f;
    #pragma unroll
    for (int s = 0; s < 16; s++) v += g_MLp[s][o];

    if (c < 16) {
        v += bmu[c];
        out[OFF_MU + n * 16 + c] = v;
    } else {
        v += blv[c - 16];
        out[OFF_LV + n * 16 + (c - 16)] = v;
    }
    mls[r][c] = v;
    __syncthreads();

    if (c < 16) {
        float z = mls[r][c] + eps[n * 16 + c] * expf(0.5f * mls[r][16 + c]);
        zs[r][c] = z;
    }
    __syncthreads();

    float p = 0.f, q = 0.f;
    #pragma unroll
    for (int l = 0; l < 16; l++) {
        float z = zs[r][l];
        p = fmaf(z, Wd1[c * 32 + l], p);
        q = fmaf(z, Wd1[c * 32 + 16 + l], q);
    }
    float qb = q + bd1[c];
    g_P[o] = p;
    g_Qb[o] = qb;

    float w = Wd2[c];
    float sv = w * p;
    float tv = w * qb;
    #pragma unroll
    for (int off = 16; off >= 1; off >>= 1) {
        sv += __shfl_xor_sync(0xffffffffu, sv, off);
        tv += __shfl_xor_sync(0xffffffffu, tv, off);
    }
    if (c == 0) {
        g_S[n] = AA_C * sv;
        g_T[n] = AA_C * tv + bd2[0];
    }
}

// ---------------------------------------------------------------------------
// Software sigmoid (no MUFU)
// ---------------------------------------------------------------------------
__device__ __forceinline__ float fast_sigmoid(float x)
{
    float ax = fminf(fabsf(x), 30.0f);
    float t = ax * -1.4426950408889634f;
    float tr = t + 12582912.0f;
    int ki = __float_as_int(tr) - 0x4B400000;
    float f = t - (tr - 12582912.0f);
    float p = 1.3333558e-3f;
    p = fmaf(p, f, 9.6181291e-3f);
    p = fmaf(p, f, 5.5504109e-2f);
    p = fmaf(p, f, 2.4022651e-1f);
    p = fmaf(p, f, 6.9314718e-1f);
    p = fmaf(p, f, 1.0f);
    float rr = p * __int_as_float((ki + 127) << 23);
    float d = 1.0f + rr;
    float y = __int_as_float(0x7EF311C3 - __float_as_int(d));
    y = y * (2.0f - d * y);
    y = y * (2.0f - d * y);
    y = y * (2.0f - d * y);
    return (x >= 0.0f) ? y : rr * y;
}

// ---------------------------------------------------------------------------
// K6: decoder via leaky split: logit = S_i + T_j + sum_h (BB*w_h)*|P_ih+Qb_jh|
// P pre-packed in smem as duplicated f32x2.
// ---------------------------------------------------------------------------
__global__ __launch_bounds__(256) void k6_decoder(
    float* __restrict__ out, const float* __restrict__ Wd2)
{
    __shared__ ull Ptd[32][66];    // [h][i] duplicated pairs
    __shared__ float Qt[32][68];   // [h][j]
    __shared__ ull ws2s[32];
    __shared__ float Ss[64];
    __shared__ float Ts[64];

    const int tid = threadIdx.x;
    const int i0 = blockIdx.y * 64;
    const int j0 = blockIdx.x * 64;

    #pragma unroll
    for (int t = tid; t < 512; t += 256) {
        int r = t >> 3, c4 = (t & 7) << 2;
        float4 pv = *(const float4*)&g_P[(size_t)(i0 + r) * 32 + c4];
        Ptd[c4 + 0][r] = pack2(pv.x); Ptd[c4 + 1][r] = pack2(pv.y);
        Ptd[c4 + 2][r] = pack2(pv.z); Ptd[c4 + 3][r] = pack2(pv.w);
        float4 qv = *(const float4*)&g_Qb[(size_t)(j0 + r) * 32 + c4];
        Qt[c4 + 0][r] = qv.x; Qt[c4 + 1][r] = qv.y;
        Qt[c4 + 2][r] = qv.z; Qt[c4 + 3][r] = qv.w;
    }
    if (tid < 32) ws2s[tid] = pack2(BB_C * Wd2[tid]);
    if (tid < 64) { Ss[tid] = g_S[i0 + tid]; Ts[tid] = g_T[j0 + tid]; }
    __syncthreads();

    const int tx = tid & 15;
    const int ty = tid >> 4;

    ull acc[4][2];
    #pragma unroll
    for (int u = 0; u < 4; u++) { acc[u][0] = 0ull; acc[u][1] = 0ull; }

    const ull AMASK = 0x7FFFFFFF7FFFFFFFull;
    #pragma unroll
    for (int h = 0; h < 32; h++) {
        ulonglong2 qv = *(const ulonglong2*)&Qt[h][tx * 4];
        ull w2 = ws2s[h];
        const ull* pr = &Ptd[h][ty * 4];
        #pragma unroll
        for (int u = 0; u < 4; u++) {
            ull pd = pr[u];
            ull t0 = add2(pd, qv.x) & AMASK;
            ull t1 = add2(pd, qv.y) & AMASK;
            fma2(acc[u][0], t0, w2);
            fma2(acc[u][1], t1, w2);
        }
    }

    #pragma unroll
    for (int u = 0; u < 4; u++) {
        int i = i0 + ty * 4 + u;
        float si = Ss[ty * 4 + u];
        float2 c0 = unpack2(acc[u][0]);
        float2 c1 = unpack2(acc[u][1]);
        float4 o4;
        o4.x = fast_sigmoid(c0.x + si + Ts[tx * 4 + 0]);
        o4.y = fast_sigmoid(c0.y + si + Ts[tx * 4 + 1]);
        o4.z = fast_sigmoid(c1.x + si + Ts[tx * 4 + 2]);
        o4.w = fast_sigmoid(c1.y + si + Ts[tx * 4 + 3]);
        *(float4*)&out[(size_t)i * NN + j0 + tx * 4] = o4;
    }
}

// ---------------------------------------------------------------------------
extern "C" void kernel_launch(void* const* d_in, const int* in_sizes, int n_in,
                              void* d_out, int out_size)
{
    const float* A_hat = (const float*)d_in[0];
    const float* X     = (const float*)d_in[1];
    const float* eps   = (const float*)d_in[2];
    const float* W1    = (const float*)d_in[3];
    const float* b1    = (const float*)d_in[4];
    const float* Wmu   = (const float*)d_in[5];
    const float* bmu   = (const float*)d_in[6];
    const float* Wlv   = (const float*)d_in[7];
    const float* blv   = (const float*)d_in[8];
    const float* Wd1   = (const float*)d_in[9];
    const float* bd1   = (const float*)d_in[10];
    const float* Wd2   = (const float*)d_in[11];
    const float* bd2   = (const float*)d_in[12];
    float* out = (float*)d_out;

    float* part = nullptr; cudaGetSymbolAddress((void**)&part, g_part);
    __nv_bfloat16* Yhi = nullptr; cudaGetSymbolAddress((void**)&Yhi, g_Yhi);
    __nv_bfloat16* Ylo = nullptr; cudaGetSymbolAddress((void**)&Ylo, g_Ylo);

    // K1: part[0..3] = X @ W1^T  (split-K 4, kslice 128)
    wgemm<0><<<dim3(2, 16, 4), 256>>>(X, DD, W1, DD, nullptr, nullptr, DD / 4, part);
    // Y(hi/lo) = sum partials, bf16-split
    reduce_split<<<NN * HH / 1024, 256>>>(part);
    // K2: part[0..3] = A_hat @ Y  (split-K 4, kslice 512)
    wgemm<1><<<dim3(2, 16, 4), 256>>>(A_hat, NN, nullptr, 0, Yhi, Ylo, NN / 4, part);
    // K3a: streaming reduce + b1 + leaky -> Hh
    k3a_hh<<<NN * HH / 1024, 256>>>(b1);
    // K3b: G = Hh @ [Wmu;Wlv]^T
    k3b_gmat<<<NN / 8, 256>>>(Wmu, Wlv);
    // K4: MLp = A_hat @ G  (split-K 16, 64-row tiles, 512 blocks)
    k4_ag<<<dim3(NN / 64, 16), 256>>>(A_hat);
    // K5: reduce + biases + mu/logvar + Z + P/Qb + S/T
    k5_epi<<<NN / 8, 256>>>(eps, bmu, blv, Wd1, bd1, Wd2, bd2, out);
    // K6: pairwise decoder
    k6_decoder<<<dim3(NN / 64, NN / 64), 256>>>(out, Wd2);
}

// round 12
// speedup vs baseline: 1.3054x; 1.0627x over previous
#include <cuda_runtime.h>
#include <cuda_bf16.h>
#include <mma.h>
#include <math.h>
#include <stdint.h>

using namespace nvcuda;

typedef unsigned long long ull;
typedef unsigned int uint;

// Problem dims (fixed)
#define NN 2048
#define DD 512
#define HH 256
#define LL 16
#define L2 32

#define OFF_MU (NN * NN)
#define OFF_LV (NN * NN + NN * LL)

#define SLOPE 0.01f
#define AA_C ((1.0f + SLOPE) * 0.5f)
#define BB_C ((1.0f - SLOPE) * 0.5f)

// Scratch (device globals; no allocation allowed)
__device__ float g_part[4 * NN * HH];          // split-K fp32 partials (8MB)
__device__ __nv_bfloat16 g_Yhi[NN * HH];       // Y = X@W1^T, bf16 split hi
__device__ __nv_bfloat16 g_Ylo[NN * HH];       // bf16 split lo
__device__ float g_Hh[NN * HH];                // leaky(A@Y + b1) fp32 (2MB)
__device__ float g_G[NN * L2];                 // Hh @ [Wmu;Wlv]^T
__device__ float g_MLp[16][NN * L2];           // split-K partials of A @ G
__device__ float g_P[NN * L2];
__device__ float g_Qb[NN * L2];
__device__ float g_S[NN];
__device__ float g_T[NN];

// ---------------------------------------------------------------------------
// f32x2 packed helpers
// ---------------------------------------------------------------------------
__device__ __forceinline__ ull pack2(float x) {
    ull r; asm("mov.b64 %0, {%1, %1};" : "=l"(r) : "f"(x)); return r;
}
__device__ __forceinline__ float2 unpack2(ull v) {
    float2 r; asm("mov.b64 {%0, %1}, %2;" : "=f"(r.x), "=f"(r.y) : "l"(v)); return r;
}
__device__ __forceinline__ void fma2(ull& d, ull a, ull b) {
    asm("fma.rn.f32x2 %0, %1, %2, %0;" : "+l"(d) : "l"(a), "l"(b));
}
__device__ __forceinline__ ull add2(ull a, ull b) {
    ull r; asm("add.rn.f32x2 %0, %1, %2;" : "=l"(r) : "l"(a), "l"(b)); return r;
}

// bf16 split: (x0,x1) -> packed hi pair + packed lo pair (elem0 in low half)
__device__ __forceinline__ void split2(float x0, float x1, uint& hp, uint& lp) {
    asm("cvt.rn.bf16x2.f32 %0, %1, %2;" : "=r"(hp) : "f"(x1), "f"(x0));
    float h0 = __int_as_float(hp << 16);
    float h1 = __int_as_float(hp & 0xFFFF0000u);
    float l0 = x0 - h0, l1 = x1 - h1;
    asm("cvt.rn.bf16x2.f32 %0, %1, %2;" : "=r"(lp) : "f"(l1), "f"(l0));
}

template <bool C, class T, class F> struct cond_t { using type = T; };
template <class T, class F> struct cond_t<false, T, F> { using type = F; };

// ---------------------------------------------------------------------------
// wgemm: C_part[z] = A[M,K](fp32, split in-kernel) @ B
//   BMODE 0: B = fp32 [N,K] row-major (col_major fragments)  [K1]
//   BMODE 1: B = bf16 hi/lo [K,N] row-major (row_major frags) [K2]
// Block tile 128x128, 8 warps (warp tile 32x64), K-chunk 32, 3-MMA bf16 split.
// Register prefetch of next chunk's global loads overlaps DRAM with MMA.
// ---------------------------------------------------------------------------
template <int BMODE>
__global__ __launch_bounds__(256) void wgemm(
    const float* __restrict__ A, int lda,
    const float* __restrict__ Bf, int ldb,
    const __nv_bfloat16* __restrict__ Bhi, const __nv_bfloat16* __restrict__ Blo,
    int kslice, float* __restrict__ Cpart)
{
    __shared__ __nv_bfloat16 sAhi[128 * 40], sAlo[128 * 40];
    __shared__ __nv_bfloat16 sBhi[128 * 40], sBlo[128 * 40]; // mode1 uses [32][136]

    const int tid = threadIdx.x;
    const int wid = tid >> 5;
    const int wm = wid & 3;
    const int wn = wid >> 2;
    const int m0 = blockIdx.y * 128;
    const int n0 = blockIdx.x * 128;
    const int k0 = blockIdx.z * kslice;

    wmma::fragment<wmma::accumulator, 16, 16, 16, float> acc[2][4];
    #pragma unroll
    for (int i = 0; i < 2; i++)
        #pragma unroll
        for (int j = 0; j < 4; j++) wmma::fill_fragment(acc[i][j], 0.0f);

    using BLay = typename cond_t<BMODE == 0, wmma::col_major, wmma::row_major>::type;

    const int arow = tid >> 3;
    const int acol = (tid & 7) << 2;
    const int b0row = tid >> 3;
    const int b0col = (tid & 7) << 2;
    const int b1row = tid >> 4;
    const int b1col = (tid & 15) << 3;

    float4 aR[4];
    float4 bR[4];
    uint4 bhR[2], blR[2];

    auto loadA = [&](int kt) {
        #pragma unroll
        for (int it = 0; it < 4; it++)
            aR[it] = *(const float4*)&A[(size_t)(m0 + it * 32 + arow) * lda + k0 + kt + acol];
    };
    auto loadB = [&](int kt) {
        if (BMODE == 0) {
            #pragma unroll
            for (int it = 0; it < 4; it++)
                bR[it] = *(const float4*)&Bf[(size_t)(n0 + it * 32 + b0row) * ldb + k0 + kt + b0col];
        } else {
            #pragma unroll
            for (int it = 0; it < 2; it++) {
                size_t gb = (size_t)(k0 + kt + it * 16 + b1row) * HH + n0 + b1col;
                bhR[it] = *(const uint4*)&Bhi[gb];
                blR[it] = *(const uint4*)&Blo[gb];
            }
        }
    };

    loadA(0);
    loadB(0);

    for (int kt = 0; kt < kslice; kt += 32) {
        #pragma unroll
        for (int it = 0; it < 4; it++) {
            int r = it * 32 + arow;
            uint h01, l01, h23, l23;
            split2(aR[it].x, aR[it].y, h01, l01);
            split2(aR[it].z, aR[it].w, h23, l23);
            *(uint2*)&sAhi[r * 40 + acol] = make_uint2(h01, h23);
            *(uint2*)&sAlo[r * 40 + acol] = make_uint2(l01, l23);
        }
        if (BMODE == 0) {
            #pragma unroll
            for (int it = 0; it < 4; it++) {
                int r = it * 32 + b0row;
                uint h01, l01, h23, l23;
                split2(bR[it].x, bR[it].y, h01, l01);
                split2(bR[it].z, bR[it].w, h23, l23);
                *(uint2*)&sBhi[r * 40 + b0col] = make_uint2(h01, h23);
                *(uint2*)&sBlo[r * 40 + b0col] = make_uint2(l01, l23);
            }
        } else {
            #pragma unroll
            for (int it = 0; it < 2; it++) {
                int r = it * 16 + b1row;
                *(uint4*)&sBhi[r * 136 + b1col] = bhR[it];
                *(uint4*)&sBlo[r * 136 + b1col] = blR[it];
            }
        }
        __syncthreads();

        if (kt + 32 < kslice) {
            loadA(kt + 32);
            loadB(kt + 32);
        }

        #pragma unroll
        for (int ks = 0; ks < 2; ks++) {
            wmma::fragment<wmma::matrix_a, 16, 16, 16, __nv_bfloat16, wmma::row_major> ah[2], al[2];
            wmma::fragment<wmma::matrix_b, 16, 16, 16, __nv_bfloat16, BLay> bh[4], bl[4];
            #pragma unroll
            for (int i = 0; i < 2; i++) {
                int row = wm * 32 + i * 16;
                wmma::load_matrix_sync(ah[i], &sAhi[row * 40 + ks * 16], 40);
                wmma::load_matrix_sync(al[i], &sAlo[row * 40 + ks * 16], 40);
            }
            #pragma unroll
            for (int j = 0; j < 4; j++) {
                int col = wn * 64 + j * 16;
                if (BMODE == 0) {
                    wmma::load_matrix_sync(bh[j], &sBhi[col * 40 + ks * 16], 40);
                    wmma::load_matrix_sync(bl[j], &sBlo[col * 40 + ks * 16], 40);
                } else {
                    wmma::load_matrix_sync(bh[j], &sBhi[(ks * 16) * 136 + col], 136);
                    wmma::load_matrix_sync(bl[j], &sBlo[(ks * 16) * 136 + col], 136);
                }
            }
            #pragma unroll
            for (int i = 0; i < 2; i++)
                #pragma unroll
                for (int j = 0; j < 4; j++) {
                    wmma::mma_sync(acc[i][j], ah[i], bh[j], acc[i][j]);
                    wmma::mma_sync(acc[i][j], ah[i], bl[j], acc[i][j]);
                    wmma::mma_sync(acc[i][j], al[i], bh[j], acc[i][j]);
                }
        }
        __syncthreads();
    }

    float* Cz = Cpart + (size_t)blockIdx.z * NN * HH;
    #pragma unroll
    for (int i = 0; i < 2; i++)
        #pragma unroll
        for (int j = 0; j < 4; j++) {
            float* dst = Cz + (size_t)(m0 + wm * 32 + i * 16) * HH + n0 + wn * 64 + j * 16;
            wmma::store_matrix_sync(dst, acc[i][j], HH, wmma::mem_row_major);
        }
}

// ---------------------------------------------------------------------------
// reduce_split: Y = sum of 4 partials, emitted as bf16 hi/lo pair arrays.
// ---------------------------------------------------------------------------
__global__ __launch_bounds__(256) void reduce_split(const float* __restrict__ part)
{
    const size_t S = (size_t)NN * HH;
    size_t i = ((size_t)blockIdx.x * 256 + threadIdx.x) * 4;
    float4 v0 = *(const float4*)&part[i];
    float4 v1 = *(const float4*)&part[S + i];
    float4 v2 = *(const float4*)&part[2 * S + i];
    float4 v3 = *(const float4*)&part[3 * S + i];
    float a = v0.x + v1.x + v2.x + v3.x;
    float b = v0.y + v1.y + v2.y + v3.y;
    float c = v0.z + v1.z + v2.z + v3.z;
    float d = v0.w + v1.w + v2.w + v3.w;
    uint h01, l01, h23, l23;
    split2(a, b, h01, l01);
    split2(c, d, h23, l23);
    *(uint2*)&g_Yhi[i] = make_uint2(h01, h23);
    *(uint2*)&g_Ylo[i] = make_uint2(l01, l23);
}

// ---------------------------------------------------------------------------
// K3a: streaming reduce 4 partials + bias + leaky -> Hh fp32.
// ---------------------------------------------------------------------------
__global__ __launch_bounds__(256) void k3a_hh(const float* __restrict__ b1)
{
    const size_t S = (size_t)NN * HH;
    size_t i = ((size_t)blockIdx.x * 256 + threadIdx.x) * 4;
    int col = (int)(i & (HH - 1));
    float4 v0 = *(const float4*)&g_part[i];
    float4 v1 = *(const float4*)&g_part[S + i];
    float4 v2 = *(const float4*)&g_part[2 * S + i];
    float4 v3 = *(const float4*)&g_part[3 * S + i];
    float4 bb = *(const float4*)&b1[col];
    float a = v0.x + v1.x + v2.x + v3.x + bb.x;
    float b = v0.y + v1.y + v2.y + v3.y + bb.y;
    float c = v0.z + v1.z + v2.z + v3.z + bb.z;
    float d = v0.w + v1.w + v2.w + v3.w + bb.w;
    *(float4*)&g_Hh[i] = make_float4(fmaxf(a, SLOPE * a), fmaxf(b, SLOPE * b),
                                     fmaxf(c, SLOPE * c), fmaxf(d, SLOPE * d));
}

// ---------------------------------------------------------------------------
// K3b: G[n, c] = sum_k Hh[n,k] * Wcat[c,k]; warp-per-row, 8 rows/block.
// ---------------------------------------------------------------------------
__global__ __launch_bounds__(256) void k3b_gmat(
    const float* __restrict__ Wmu, const float* __restrict__ Wlv)
{
    __shared__ float Ws[32][260];
    const int tid = threadIdx.x;
    const int m0 = blockIdx.x * 8;

    #pragma unroll
    for (int it = 0; it < 8; it++) {
        int idx = tid + it * 256;
        int c = idx >> 6, k4 = (idx & 63) << 2;
        const float* src = (c < 16) ? &Wmu[c * 256 + k4] : &Wlv[(c - 16) * 256 + k4];
        *(float4*)&Ws[c][k4] = *(const float4*)src;
    }
    __syncthreads();

    const int w = tid >> 5;
    const int c = tid & 31;
    const float4* hr = (const float4*)&g_Hh[(size_t)(m0 + w) * 256];
    float acc = 0.f;
    #pragma unroll 8
    for (int k4 = 0; k4 < 64; k4++) {
        float4 h = hr[k4];
        float4 ww = *(const float4*)&Ws[c][k4 * 4];
        acc = fmaf(h.x, ww.x, acc);
        acc = fmaf(h.y, ww.y, acc);
        acc = fmaf(h.z, ww.z, acc);
        acc = fmaf(h.w, ww.w, acc);
    }
    g_G[(m0 + w) * 32 + c] = acc;
}

// ---------------------------------------------------------------------------
// K4: split-K (16) A @ G. Tile 128 rows x 32 cols, BK=16, grid (16,16)=256
// blocks (~2 CTAs/SM for latency hiding). Micro 4x4 via f32x2.
// ---------------------------------------------------------------------------
__global__ __launch_bounds__(256) void k4_ag(const float* __restrict__ A)
{
    __shared__ float As[16][132];
    __shared__ float Bs[16][36];

    const int tid = threadIdx.x;
    const int m0 = blockIdx.x * 128;
    const int k0 = blockIdx.y * 128;

    const int ar = tid >> 2;            // 0..63
    const int ac = (tid & 3) << 2;
    const float* Ap = A + (size_t)(m0 + ar) * NN + k0 + ac;

    const int tx = tid & 7;             // col quad (2 f32x2)
    const int ty = tid >> 3;            // 0..31 -> rows ty*4..ty*4+3

    ull acc[4][2];
    #pragma unroll
    for (int u = 0; u < 4; u++) { acc[u][0] = 0ull; acc[u][1] = 0ull; }

    float4 a4[2];
    a4[0] = *(const float4*)Ap;
    a4[1] = *(const float4*)(Ap + (size_t)64 * NN);

    for (int kt = 0; kt < 128; kt += 16) {
        #pragma unroll
        for (int j = 0; j < 2; j++) {
            As[ac + 0][ar + 64 * j] = a4[j].x; As[ac + 1][ar + 64 * j] = a4[j].y;
            As[ac + 2][ar + 64 * j] = a4[j].z; As[ac + 3][ar + 64 * j] = a4[j].w;
        }
        if (tid < 128) {
            int brr = tid >> 3, bcc = (tid & 7) << 2;
            *(float4*)&Bs[brr][bcc] =
                *(const float4*)&g_G[(size_t)(k0 + kt + brr) * 32 + bcc];
        }
        __syncthreads();

        if (kt + 16 < 128) {
            a4[0] = *(const float4*)(Ap + kt + 16);
            a4[1] = *(const float4*)(Ap + (size_t)64 * NN + kt + 16);
        }

        #pragma unroll
        for (int kk = 0; kk < 16; kk++) {
            float4 av = *(const float4*)&As[kk][ty * 4];
            ulonglong2 bv = *(const ulonglong2*)&Bs[kk][tx * 4];
            ull pa[4];
            pa[0] = pack2(av.x); pa[1] = pack2(av.y);
            pa[2] = pack2(av.z); pa[3] = pack2(av.w);
            #pragma unroll
            for (int u = 0; u < 4; u++) {
                fma2(acc[u][0], pa[u], bv.x);
                fma2(acc[u][1], pa[u], bv.y);
            }
        }
        __syncthreads();
    }

    float* outp = g_MLp[blockIdx.y];
    #pragma unroll
    for (int u = 0; u < 4; u++) {
        int row = m0 + ty * 4 + u;
        float2 c0 = unpack2(acc[u][0]);
        float2 c1 = unpack2(acc[u][1]);
        *(float4*)&outp[(size_t)row * 32 + tx * 4] =
            make_float4(c0.x, c0.y, c1.x, c1.y);
    }
}

// ---------------------------------------------------------------------------
// K5: reduce 16 partials, biases, mu/logvar, reparameterize, P/Qb, S/T.
// ---------------------------------------------------------------------------
__global__ __launch_bounds__(256) void k5_epi(
    const float* __restrict__ eps, const float* __restrict__ bmu,
    const float* __restrict__ blv, const float* __restrict__ Wd1,
    const float* __restrict__ bd1, const float* __restrict__ Wd2,
    const float* __restrict__ bd2, float* __restrict__ out)
{
    __shared__ float mls[8][32];
    __shared__ float zs[8][16];
    const int r = threadIdx.x >> 5;
    const int c = threadIdx.x & 31;
    const int n = blockIdx.x * 8 + r;
    const size_t o = (size_t)n * 32 + c;

    float v = 0.f;
    #pragma unroll
    for (int s = 0; s < 16; s++) v += g_MLp[s][o];

    if (c < 16) {
        v += bmu[c];
        out[OFF_MU + n * 16 + c] = v;
    } else {
        v += blv[c - 16];
        out[OFF_LV + n * 16 + (c - 16)] = v;
    }
    mls[r][c] = v;
    __syncthreads();

    if (c < 16) {
        float z = mls[r][c] + eps[n * 16 + c] * expf(0.5f * mls[r][16 + c]);
        zs[r][c] = z;
    }
    __syncthreads();

    float p = 0.f, q = 0.f;
    #pragma unroll
    for (int l = 0; l < 16; l++) {
        float z = zs[r][l];
        p = fmaf(z, Wd1[c * 32 + l], p);
        q = fmaf(z, Wd1[c * 32 + 16 + l], q);
    }
    float qb = q + bd1[c];
    g_P[o] = p;
    g_Qb[o] = qb;

    float w = Wd2[c];
    float sv = w * p;
    float tv = w * qb;
    #pragma unroll
    for (int off = 16; off >= 1; off >>= 1) {
        sv += __shfl_xor_sync(0xffffffffu, sv, off);
        tv += __shfl_xor_sync(0xffffffffu, tv, off);
    }
    if (c == 0) {
        g_S[n] = AA_C * sv;
        g_T[n] = AA_C * tv + bd2[0];
    }
}

// ---------------------------------------------------------------------------
// Software sigmoid (no MUFU)
// ---------------------------------------------------------------------------
__device__ __forceinline__ float fast_sigmoid(float x)
{
    float ax = fminf(fabsf(x), 30.0f);
    float t = ax * -1.4426950408889634f;
    float tr = t + 12582912.0f;
    int ki = __float_as_int(tr) - 0x4B400000;
    float f = t - (tr - 12582912.0f);
    float p = 1.3333558e-3f;
    p = fmaf(p, f, 9.6181291e-3f);
    p = fmaf(p, f, 5.5504109e-2f);
    p = fmaf(p, f, 2.4022651e-1f);
    p = fmaf(p, f, 6.9314718e-1f);
    p = fmaf(p, f, 1.0f);
    float rr = p * __int_as_float((ki + 127) << 23);
    float d = 1.0f + rr;
    float y = __int_as_float(0x7EF311C3 - __float_as_int(d));
    y = y * (2.0f - d * y);
    y = y * (2.0f - d * y);
    y = y * (2.0f - d * y);
    return (x >= 0.0f) ? y : rr * y;
}

// ---------------------------------------------------------------------------
// K6: decoder via leaky split: logit = S_i + T_j + sum_h (BB*w_h)*|P_ih+Qb_jh|
// P pre-packed in smem as duplicated f32x2.
// ---------------------------------------------------------------------------
__global__ __launch_bounds__(256) void k6_decoder(
    float* __restrict__ out, const float* __restrict__ Wd2)
{
    __shared__ ull Ptd[32][66];    // [h][i] duplicated pairs
    __shared__ float Qt[32][68];   // [h][j]
    __shared__ ull ws2s[32];
    __shared__ float Ss[64];
    __shared__ float Ts[64];

    const int tid = threadIdx.x;
    const int i0 = blockIdx.y * 64;
    const int j0 = blockIdx.x * 64;

    #pragma unroll
    for (int t = tid; t < 512; t += 256) {
        int r = t >> 3, c4 = (t & 7) << 2;
        float4 pv = *(const float4*)&g_P[(size_t)(i0 + r) * 32 + c4];
        Ptd[c4 + 0][r] = pack2(pv.x); Ptd[c4 + 1][r] = pack2(pv.y);
        Ptd[c4 + 2][r] = pack2(pv.z); Ptd[c4 + 3][r] = pack2(pv.w);
        float4 qv = *(const float4*)&g_Qb[(size_t)(j0 + r) * 32 + c4];
        Qt[c4 + 0][r] = qv.x; Qt[c4 + 1][r] = qv.y;
        Qt[c4 + 2][r] = qv.z; Qt[c4 + 3][r] = qv.w;
    }
    if (tid < 32) ws2s[tid] = pack2(BB_C * Wd2[tid]);
    if (tid < 64) { Ss[tid] = g_S[i0 + tid]; Ts[tid] = g_T[j0 + tid]; }
    __syncthreads();

    const int tx = tid & 15;
    const int ty = tid >> 4;

    ull acc[4][2];
    #pragma unroll
    for (int u = 0; u < 4; u++) { acc[u][0] = 0ull; acc[u][1] = 0ull; }

    const ull AMASK = 0x7FFFFFFF7FFFFFFFull;
    #pragma unroll
    for (int h = 0; h < 32; h++) {
        ulonglong2 qv = *(const ulonglong2*)&Qt[h][tx * 4];
        ull w2 = ws2s[h];
        const ull* pr = &Ptd[h][ty * 4];
        #pragma unroll
        for (int u = 0; u < 4; u++) {
            ull pd = pr[u];
            ull t0 = add2(pd, qv.x) & AMASK;
            ull t1 = add2(pd, qv.y) & AMASK;
            fma2(acc[u][0], t0, w2);
            fma2(acc[u][1], t1, w2);
        }
    }

    #pragma unroll
    for (int u = 0; u < 4; u++) {
        int i = i0 + ty * 4 + u;
        float si = Ss[ty * 4 + u];
        float2 c0 = unpack2(acc[u][0]);
        float2 c1 = unpack2(acc[u][1]);
        float4 o4;
        o4.x = fast_sigmoid(c0.x + si + Ts[tx * 4 + 0]);
        o4.y = fast_sigmoid(c0.y + si + Ts[tx * 4 + 1]);
        o4.z = fast_sigmoid(c1.x + si + Ts[tx * 4 + 2]);
        o4.w = fast_sigmoid(c1.y + si + Ts[tx * 4 + 3]);
        *(float4*)&out[(size_t)i * NN + j0 + tx * 4] = o4;
    }
}

// ---------------------------------------------------------------------------
extern "C" void kernel_launch(void* const* d_in, const int* in_sizes, int n_in,
                              void* d_out, int out_size)
{
    const float* A_hat = (const float*)d_in[0];
    const float* X     = (const float*)d_in[1];
    const float* eps   = (const float*)d_in[2];
    const float* W1    = (const float*)d_in[3];
    const float* b1    = (const float*)d_in[4];
    const float* Wmu   = (const float*)d_in[5];
    const float* bmu   = (const float*)d_in[6];
    const float* Wlv   = (const float*)d_in[7];
    const float* blv   = (const float*)d_in[8];
    const float* Wd1   = (const float*)d_in[9];
    const float* bd1   = (const float*)d_in[10];
    const float* Wd2   = (const float*)d_in[11];
    const float* bd2   = (const float*)d_in[12];
    float* out = (float*)d_out;

    float* part = nullptr; cudaGetSymbolAddress((void**)&part, g_part);
    __nv_bfloat16* Yhi = nullptr; cudaGetSymbolAddress((void**)&Yhi, g_Yhi);
    __nv_bfloat16* Ylo = nullptr; cudaGetSymbolAddress((void**)&Ylo, g_Ylo);

    // K1: part[0..3] = X @ W1^T  (split-K 4, kslice 128)
    wgemm<0><<<dim3(2, 16, 4), 256>>>(X, DD, W1, DD, nullptr, nullptr, DD / 4, part);
    // Y(hi/lo) = sum partials, bf16-split
    reduce_split<<<NN * HH / 1024, 256>>>(part);
    // K2: part[0..3] = A_hat @ Y  (split-K 4, kslice 512)
    wgemm<1><<<dim3(2, 16, 4), 256>>>(A_hat, NN, nullptr, 0, Yhi, Ylo, NN / 4, part);
    // K3a: streaming reduce + b1 + leaky -> Hh
    k3a_hh<<<NN * HH / 1024, 256>>>(b1);
    // K3b: G = Hh @ [Wmu;Wlv]^T
    k3b_gmat<<<NN / 8, 256>>>(Wmu, Wlv);
    // K4: MLp = A_hat @ G  (split-K 16, 128-row tiles, grid 256)
    k4_ag<<<dim3(NN / 128, 16), 256>>>(A_hat);
    // K5: reduce + biases + mu/logvar + Z + P/Qb + S/T
    k5_epi<<<NN / 8, 256>>>(eps, bmu, blv, Wd1, bd1, Wd2, bd2, out);
    // K6: pairwise decoder
    k6_decoder<<<dim3(NN / 64, NN / 64), 256>>>(out, Wd2);
}

// round 13
// speedup vs baseline: 1.3118x; 1.0048x over previous
#include <cuda_runtime.h>
#include <cuda_bf16.h>
#include <mma.h>
#include <math.h>
#include <stdint.h>

using namespace nvcuda;

typedef unsigned long long ull;
typedef unsigned int uint;

// Problem dims (fixed)
#define NN 2048
#define DD 512
#define HH 256
#define LL 16
#define L2 32

#define OFF_MU (NN * NN)
#define OFF_LV (NN * NN + NN * LL)

#define SLOPE 0.01f
#define AA_C ((1.0f + SLOPE) * 0.5f)
#define BB_C ((1.0f - SLOPE) * 0.5f)

// Scratch (device globals; no allocation allowed)
__device__ float g_part[4 * NN * HH];          // split-K fp32 partials (8MB)
__device__ __nv_bfloat16 g_Yhi[NN * HH];       // Y = X@W1^T, bf16 split hi
__device__ __nv_bfloat16 g_Ylo[NN * HH];       // bf16 split lo
__device__ float g_Hh[NN * HH];                // leaky(A@Y + b1) fp32 (2MB)
__device__ float g_G[NN * L2];                 // Hh @ [Wmu;Wlv]^T
__device__ float g_MLp[16][NN * L2];           // split-K partials of A @ G
__device__ float g_P[NN * L2];
__device__ float g_Qb[NN * L2];
__device__ float g_S[NN];
__device__ float g_T[NN];

// ---------------------------------------------------------------------------
// f32x2 packed helpers
// ---------------------------------------------------------------------------
__device__ __forceinline__ ull pack2(float x) {
    ull r; asm("mov.b64 %0, {%1, %1};" : "=l"(r) : "f"(x)); return r;
}
__device__ __forceinline__ float2 unpack2(ull v) {
    float2 r; asm("mov.b64 {%0, %1}, %2;" : "=f"(r.x), "=f"(r.y) : "l"(v)); return r;
}
__device__ __forceinline__ void fma2(ull& d, ull a, ull b) {
    asm("fma.rn.f32x2 %0, %1, %2, %0;" : "+l"(d) : "l"(a), "l"(b));
}
__device__ __forceinline__ ull add2(ull a, ull b) {
    ull r; asm("add.rn.f32x2 %0, %1, %2;" : "=l"(r) : "l"(a), "l"(b)); return r;
}

// bf16 split: (x0,x1) -> packed hi pair + packed lo pair (elem0 in low half)
__device__ __forceinline__ void split2(float x0, float x1, uint& hp, uint& lp) {
    asm("cvt.rn.bf16x2.f32 %0, %1, %2;" : "=r"(hp) : "f"(x1), "f"(x0));
    float h0 = __int_as_float(hp << 16);
    float h1 = __int_as_float(hp & 0xFFFF0000u);
    float l0 = x0 - h0, l1 = x1 - h1;
    asm("cvt.rn.bf16x2.f32 %0, %1, %2;" : "=r"(lp) : "f"(l1), "f"(l0));
}

template <bool C, class T, class F> struct cond_t { using type = T; };
template <class T, class F> struct cond_t<false, T, F> { using type = F; };

// ---------------------------------------------------------------------------
// wgemm: C_part[z] = A[M,K](fp32, split in-kernel) @ B
//   BMODE 0: B = fp32 [N,K] row-major (col_major fragments)  [K1]
//   BMODE 1: B = bf16 hi/lo [K,N] row-major (row_major frags) [K2]
// Block tile 128x128, 8 warps (warp tile 32x64), K-chunk 32, 3-MMA bf16 split.
// DOUBLE-BUFFERED dynamic smem: one __syncthreads per chunk; the convert+store
// of chunk k+1 overlaps the MMA of chunk k; global prefetch covers LDG latency.
// ---------------------------------------------------------------------------
#define STAGE_BYTES 42240   // Ahi 10240 | Alo 10240 | Bhi 10880 | Blo 10880
#define WG_SMEM (2 * STAGE_BYTES)

template <int BMODE>
__global__ __launch_bounds__(256) void wgemm(
    const float* __restrict__ A, int lda,
    const float* __restrict__ Bf, int ldb,
    const __nv_bfloat16* __restrict__ Bhi, const __nv_bfloat16* __restrict__ Blo,
    int kslice, float* __restrict__ Cpart)
{
    extern __shared__ char dynsm[];

    const int tid = threadIdx.x;
    const int wid = tid >> 5;
    const int wm = wid & 3;
    const int wn = wid >> 2;
    const int m0 = blockIdx.y * 128;
    const int n0 = blockIdx.x * 128;
    const int k0 = blockIdx.z * kslice;

    wmma::fragment<wmma::accumulator, 16, 16, 16, float> acc[2][4];
    #pragma unroll
    for (int i = 0; i < 2; i++)
        #pragma unroll
        for (int j = 0; j < 4; j++) wmma::fill_fragment(acc[i][j], 0.0f);

    using BLay = typename cond_t<BMODE == 0, wmma::col_major, wmma::row_major>::type;

    const int arow = tid >> 3;
    const int acol = (tid & 7) << 2;
    const int b0row = tid >> 3;
    const int b0col = (tid & 7) << 2;
    const int b1row = tid >> 4;
    const int b1col = (tid & 15) << 3;

    float4 aR[4];
    float4 bR[4];
    uint4 bhR[2], blR[2];

    auto sAhi = [&](int s) { return (__nv_bfloat16*)(dynsm + s * STAGE_BYTES); };
    auto sAlo = [&](int s) { return (__nv_bfloat16*)(dynsm + s * STAGE_BYTES + 10240); };
    auto sBhi = [&](int s) { return (__nv_bfloat16*)(dynsm + s * STAGE_BYTES + 20480); };
    auto sBlo = [&](int s) { return (__nv_bfloat16*)(dynsm + s * STAGE_BYTES + 31360); };

    auto loadA = [&](int kt) {
        #pragma unroll
        for (int it = 0; it < 4; it++)
            aR[it] = *(const float4*)&A[(size_t)(m0 + it * 32 + arow) * lda + k0 + kt + acol];
    };
    auto loadB = [&](int kt) {
        if (BMODE == 0) {
            #pragma unroll
            for (int it = 0; it < 4; it++)
                bR[it] = *(const float4*)&Bf[(size_t)(n0 + it * 32 + b0row) * ldb + k0 + kt + b0col];
        } else {
            #pragma unroll
            for (int it = 0; it < 2; it++) {
                size_t gb = (size_t)(k0 + kt + it * 16 + b1row) * HH + n0 + b1col;
                bhR[it] = *(const uint4*)&Bhi[gb];
                blR[it] = *(const uint4*)&Blo[gb];
            }
        }
    };
    auto storeStage = [&](int s) {
        __nv_bfloat16* ah = sAhi(s);
        __nv_bfloat16* al = sAlo(s);
        __nv_bfloat16* bh = sBhi(s);
        __nv_bfloat16* bl = sBlo(s);
        #pragma unroll
        for (int it = 0; it < 4; it++) {
            int r = it * 32 + arow;
            uint h01, l01, h23, l23;
            split2(aR[it].x, aR[it].y, h01, l01);
            split2(aR[it].z, aR[it].w, h23, l23);
            *(uint2*)&ah[r * 40 + acol] = make_uint2(h01, h23);
            *(uint2*)&al[r * 40 + acol] = make_uint2(l01, l23);
        }
        if (BMODE == 0) {
            #pragma unroll
            for (int it = 0; it < 4; it++) {
                int r = it * 32 + b0row;
                uint h01, l01, h23, l23;
                split2(bR[it].x, bR[it].y, h01, l01);
                split2(bR[it].z, bR[it].w, h23, l23);
                *(uint2*)&bh[r * 40 + b0col] = make_uint2(h01, h23);
                *(uint2*)&bl[r * 40 + b0col] = make_uint2(l01, l23);
            }
        } else {
            #pragma unroll
            for (int it = 0; it < 2; it++) {
                int r = it * 16 + b1row;
                *(uint4*)&bh[r * 136 + b1col] = bhR[it];
                *(uint4*)&bl[r * 136 + b1col] = blR[it];
            }
        }
    };

    loadA(0);
    loadB(0);
    storeStage(0);
    __syncthreads();

    int cur = 0;
    for (int kt = 0; kt < kslice; kt += 32) {
        const bool more = (kt + 32 < kslice);
        if (more) {                       // LDGs in flight during MMA below
            loadA(kt + 32);
            loadB(kt + 32);
        }

        const __nv_bfloat16* ah_s = sAhi(cur);
        const __nv_bfloat16* al_s = sAlo(cur);
        const __nv_bfloat16* bh_s = sBhi(cur);
        const __nv_bfloat16* bl_s = sBlo(cur);

        #pragma unroll
        for (int ks = 0; ks < 2; ks++) {
            wmma::fragment<wmma::matrix_a, 16, 16, 16, __nv_bfloat16, wmma::row_major> ah[2], al[2];
            wmma::fragment<wmma::matrix_b, 16, 16, 16, __nv_bfloat16, BLay> bh[4], bl[4];
            #pragma unroll
            for (int i = 0; i < 2; i++) {
                int row = wm * 32 + i * 16;
                wmma::load_matrix_sync(ah[i], &ah_s[row * 40 + ks * 16], 40);
                wmma::load_matrix_sync(al[i], &al_s[row * 40 + ks * 16], 40);
            }
            #pragma unroll
            for (int j = 0; j < 4; j++) {
                int col = wn * 64 + j * 16;
                if (BMODE == 0) {
                    wmma::load_matrix_sync(bh[j], &bh_s[col * 40 + ks * 16], 40);
                    wmma::load_matrix_sync(bl[j], &bl_s[col * 40 + ks * 16], 40);
                } else {
                    wmma::load_matrix_sync(bh[j], &bh_s[(ks * 16) * 136 + col], 136);
                    wmma::load_matrix_sync(bl[j], &bl_s[(ks * 16) * 136 + col], 136);
                }
            }
            #pragma unroll
            for (int i = 0; i < 2; i++)
                #pragma unroll
                for (int j = 0; j < 4; j++) {
                    wmma::mma_sync(acc[i][j], ah[i], bh[j], acc[i][j]);
                    wmma::mma_sync(acc[i][j], ah[i], bl[j], acc[i][j]);
                    wmma::mma_sync(acc[i][j], al[i], bh[j], acc[i][j]);
                }
        }

        if (more) storeStage(cur ^ 1);    // write NEXT buffer; no conflict
        __syncthreads();                  // one sync per chunk
        cur ^= 1;
    }

    float* Cz = Cpart + (size_t)blockIdx.z * NN * HH;
    #pragma unroll
    for (int i = 0; i < 2; i++)
        #pragma unroll
        for (int j = 0; j < 4; j++) {
            float* dst = Cz + (size_t)(m0 + wm * 32 + i * 16) * HH + n0 + wn * 64 + j * 16;
            wmma::store_matrix_sync(dst, acc[i][j], HH, wmma::mem_row_major);
        }
}

// ---------------------------------------------------------------------------
// reduce_split: Y = sum of 4 partials, emitted as bf16 hi/lo pair arrays.
// ---------------------------------------------------------------------------
__global__ __launch_bounds__(256) void reduce_split(const float* __restrict__ part)
{
    const size_t S = (size_t)NN * HH;
    size_t i = ((size_t)blockIdx.x * 256 + threadIdx.x) * 4;
    float4 v0 = *(const float4*)&part[i];
    float4 v1 = *(const float4*)&part[S + i];
    float4 v2 = *(const float4*)&part[2 * S + i];
    float4 v3 = *(const float4*)&part[3 * S + i];
    float a = v0.x + v1.x + v2.x + v3.x;
    float b = v0.y + v1.y + v2.y + v3.y;
    float c = v0.z + v1.z + v2.z + v3.z;
    float d = v0.w + v1.w + v2.w + v3.w;
    uint h01, l01, h23, l23;
    split2(a, b, h01, l01);
    split2(c, d, h23, l23);
    *(uint2*)&g_Yhi[i] = make_uint2(h01, h23);
    *(uint2*)&g_Ylo[i] = make_uint2(l01, l23);
}

// ---------------------------------------------------------------------------
// K3a: streaming reduce 4 partials + bias + leaky -> Hh fp32.
// 2 float4 per thread per slice (MLP 8) for latency hiding; grid 256.
// ---------------------------------------------------------------------------
__global__ __launch_bounds__(256) void k3a_hh(const float* __restrict__ b1)
{
    const size_t S = (size_t)NN * HH;
    size_t base = ((size_t)blockIdx.x * 256 + threadIdx.x) * 8;
    #pragma unroll
    for (int g = 0; g < 2; g++) {
        size_t i = base + g * 4;
        int col = (int)(i & (HH - 1));
        float4 v0 = *(const float4*)&g_part[i];
        float4 v1 = *(const float4*)&g_part[S + i];
        float4 v2 = *(const float4*)&g_part[2 * S + i];
        float4 v3 = *(const float4*)&g_part[3 * S + i];
        float4 bb = *(const float4*)&b1[col];
        float a = v0.x + v1.x + v2.x + v3.x + bb.x;
        float b = v0.y + v1.y + v2.y + v3.y + bb.y;
        float c = v0.z + v1.z + v2.z + v3.z + bb.z;
        float d = v0.w + v1.w + v2.w + v3.w + bb.w;
        *(float4*)&g_Hh[i] = make_float4(fmaxf(a, SLOPE * a), fmaxf(b, SLOPE * b),
                                         fmaxf(c, SLOPE * c), fmaxf(d, SLOPE * d));
    }
}

// ---------------------------------------------------------------------------
// K3b: G[n, c] = sum_k Hh[n,k] * Wcat[c,k]; warp-per-row, 8 rows/block.
// ---------------------------------------------------------------------------
__global__ __launch_bounds__(256) void k3b_gmat(
    const float* __restrict__ Wmu, const float* __restrict__ Wlv)
{
    __shared__ float Ws[32][260];
    const int tid = threadIdx.x;
    const int m0 = blockIdx.x * 8;

    #pragma unroll
    for (int it = 0; it < 8; it++) {
        int idx = tid + it * 256;
        int c = idx >> 6, k4 = (idx & 63) << 2;
        const float* src = (c < 16) ? &Wmu[c * 256 + k4] : &Wlv[(c - 16) * 256 + k4];
        *(float4*)&Ws[c][k4] = *(const float4*)src;
    }
    __syncthreads();

    const int w = tid >> 5;
    const int c = tid & 31;
    const float4* hr = (const float4*)&g_Hh[(size_t)(m0 + w) * 256];
    float acc = 0.f;
    #pragma unroll 8
    for (int k4 = 0; k4 < 64; k4++) {
        float4 h = hr[k4];
        float4 ww = *(const float4*)&Ws[c][k4 * 4];
        acc = fmaf(h.x, ww.x, acc);
        acc = fmaf(h.y, ww.y, acc);
        acc = fmaf(h.z, ww.z, acc);
        acc = fmaf(h.w, ww.w, acc);
    }
    g_G[(m0 + w) * 32 + c] = acc;
}

// ---------------------------------------------------------------------------
// K4: split-K (16) A @ G. Tile 128 rows x 32 cols, BK=16, grid (16,16)=256
// blocks (~2 CTAs/SM for latency hiding). Micro 4x4 via f32x2.
// ---------------------------------------------------------------------------
__global__ __launch_bounds__(256) void k4_ag(const float* __restrict__ A)
{
    __shared__ float As[16][132];
    __shared__ float Bs[16][36];

    const int tid = threadIdx.x;
    const int m0 = blockIdx.x * 128;
    const int k0 = blockIdx.y * 128;

    const int ar = tid >> 2;            // 0..63
    const int ac = (tid & 3) << 2;
    const float* Ap = A + (size_t)(m0 + ar) * NN + k0 + ac;

    const int tx = tid & 7;             // col quad (2 f32x2)
    const int ty = tid >> 3;            // 0..31 -> rows ty*4..ty*4+3

    ull acc[4][2];
    #pragma unroll
    for (int u = 0; u < 4; u++) { acc[u][0] = 0ull; acc[u][1] = 0ull; }

    float4 a4[2];
    a4[0] = *(const float4*)Ap;
    a4[1] = *(const float4*)(Ap + (size_t)64 * NN);

    for (int kt = 0; kt < 128; kt += 16) {
        #pragma unroll
        for (int j = 0; j < 2; j++) {
            As[ac + 0][ar + 64 * j] = a4[j].x; As[ac + 1][ar + 64 * j] = a4[j].y;
            As[ac + 2][ar + 64 * j] = a4[j].z; As[ac + 3][ar + 64 * j] = a4[j].w;
        }
        if (tid < 128) {
            int brr = tid >> 3, bcc = (tid & 7) << 2;
            *(float4*)&Bs[brr][bcc] =
                *(const float4*)&g_G[(size_t)(k0 + kt + brr) * 32 + bcc];
        }
        __syncthreads();

        if (kt + 16 < 128) {
            a4[0] = *(const float4*)(Ap + kt + 16);
            a4[1] = *(const float4*)(Ap + (size_t)64 * NN + kt + 16);
        }

        #pragma unroll
        for (int kk = 0; kk < 16; kk++) {
            float4 av = *(const float4*)&As[kk][ty * 4];
            ulonglong2 bv = *(const ulonglong2*)&Bs[kk][tx * 4];
            ull pa[4];
            pa[0] = pack2(av.x); pa[1] = pack2(av.y);
            pa[2] = pack2(av.z); pa[3] = pack2(av.w);
            #pragma unroll
            for (int u = 0; u < 4; u++) {
                fma2(acc[u][0], pa[u], bv.x);
                fma2(acc[u][1], pa[u], bv.y);
            }
        }
        __syncthreads();
    }

    float* outp = g_MLp[blockIdx.y];
    #pragma unroll
    for (int u = 0; u < 4; u++) {
        int row = m0 + ty * 4 + u;
        float2 c0 = unpack2(acc[u][0]);
        float2 c1 = unpack2(acc[u][1]);
        *(float4*)&outp[(size_t)row * 32 + tx * 4] =
            make_float4(c0.x, c0.y, c1.x, c1.y);
    }
}

// ---------------------------------------------------------------------------
// K5: reduce 16 partials, biases, mu/logvar, reparameterize, P/Qb, S/T.
// ---------------------------------------------------------------------------
__global__ __launch_bounds__(256) void k5_epi(
    const float* __restrict__ eps, const float* __restrict__ bmu,
    const float* __restrict__ blv, const float* __restrict__ Wd1,
    const float* __restrict__ bd1, const float* __restrict__ Wd2,
    const float* __restrict__ bd2, float* __restrict__ out)
{
    __shared__ float mls[8][32];
    __shared__ float zs[8][16];
    const int r = threadIdx.x >> 5;
    const int c = threadIdx.x & 31;
    const int n = blockIdx.x * 8 + r;
    const size_t o = (size_t)n * 32 + c;

    float v = 0.f;
    #pragma unroll
    for (int s = 0; s < 16; s++) v += g_MLp[s][o];

    if (c < 16) {
        v += bmu[c];
        out[OFF_MU + n * 16 + c] = v;
    } else {
        v += blv[c - 16];
        out[OFF_LV + n * 16 + (c - 16)] = v;
    }
    mls[r][c] = v;
    __syncthreads();

    if (c < 16) {
        float z = mls[r][c] + eps[n * 16 + c] * expf(0.5f * mls[r][16 + c]);
        zs[r][c] = z;
    }
    __syncthreads();

    float p = 0.f, q = 0.f;
    #pragma unroll
    for (int l = 0; l < 16; l++) {
        float z = zs[r][l];
        p = fmaf(z, Wd1[c * 32 + l], p);
        q = fmaf(z, Wd1[c * 32 + 16 + l], q);
    }
    float qb = q + bd1[c];
    g_P[o] = p;
    g_Qb[o] = qb;

    float w = Wd2[c];
    float sv = w * p;
    float tv = w * qb;
    #pragma unroll
    for (int off = 16; off >= 1; off >>= 1) {
        sv += __shfl_xor_sync(0xffffffffu, sv, off);
        tv += __shfl_xor_sync(0xffffffffu, tv, off);
    }
    if (c == 0) {
        g_S[n] = AA_C * sv;
        g_T[n] = AA_C * tv + bd2[0];
    }
}

// ---------------------------------------------------------------------------
// Software sigmoid (no MUFU)
// ---------------------------------------------------------------------------
__device__ __forceinline__ float fast_sigmoid(float x)
{
    float ax = fminf(fabsf(x), 30.0f);
    float t = ax * -1.4426950408889634f;
    float tr = t + 12582912.0f;
    int ki = __float_as_int(tr) - 0x4B400000;
    float f = t - (tr - 12582912.0f);
    float p = 1.3333558e-3f;
    p = fmaf(p, f, 9.6181291e-3f);
    p = fmaf(p, f, 5.5504109e-2f);
    p = fmaf(p, f, 2.4022651e-1f);
    p = fmaf(p, f, 6.9314718e-1f);
    p = fmaf(p, f, 1.0f);
    float rr = p * __int_as_float((ki + 127) << 23);
    float d = 1.0f + rr;
    float y = __int_as_float(0x7EF311C3 - __float_as_int(d));
    y = y * (2.0f - d * y);
    y = y * (2.0f - d * y);
    y = y * (2.0f - d * y);
    return (x >= 0.0f) ? y : rr * y;
}

// ---------------------------------------------------------------------------
// K6: decoder via leaky split: logit = S_i + T_j + sum_h (BB*w_h)*|P_ih+Qb_jh|
// P pre-packed in smem as duplicated f32x2.
// ---------------------------------------------------------------------------
__global__ __launch_bounds__(256) void k6_decoder(
    float* __restrict__ out, const float* __restrict__ Wd2)
{
    __shared__ ull Ptd[32][66];    // [h][i] duplicated pairs
    __shared__ float Qt[32][68];   // [h][j]
    __shared__ ull ws2s[32];
    __shared__ float Ss[64];
    __shared__ float Ts[64];

    const int tid = threadIdx.x;
    const int i0 = blockIdx.y * 64;
    const int j0 = blockIdx.x * 64;

    #pragma unroll
    for (int t = tid; t < 512; t += 256) {
        int r = t >> 3, c4 = (t & 7) << 2;
        float4 pv = *(const float4*)&g_P[(size_t)(i0 + r) * 32 + c4];
        Ptd[c4 + 0][r] = pack2(pv.x); Ptd[c4 + 1][r] = pack2(pv.y);
        Ptd[c4 + 2][r] = pack2(pv.z); Ptd[c4 + 3][r] = pack2(pv.w);
        float4 qv = *(const float4*)&g_Qb[(size_t)(j0 + r) * 32 + c4];
        Qt[c4 + 0][r] = qv.x; Qt[c4 + 1][r] = qv.y;
        Qt[c4 + 2][r] = qv.z; Qt[c4 + 3][r] = qv.w;
    }
    if (tid < 32) ws2s[tid] = pack2(BB_C * Wd2[tid]);
    if (tid < 64) { Ss[tid] = g_S[i0 + tid]; Ts[tid] = g_T[j0 + tid]; }
    __syncthreads();

    const int tx = tid & 15;
    const int ty = tid >> 4;

    ull acc[4][2];
    #pragma unroll
    for (int u = 0; u < 4; u++) { acc[u][0] = 0ull; acc[u][1] = 0ull; }

    const ull AMASK = 0x7FFFFFFF7FFFFFFFull;
    #pragma unroll
    for (int h = 0; h < 32; h++) {
        ulonglong2 qv = *(const ulonglong2*)&Qt[h][tx * 4];
        ull w2 = ws2s[h];
        const ull* pr = &Ptd[h][ty * 4];
        #pragma unroll
        for (int u = 0; u < 4; u++) {
            ull pd = pr[u];
            ull t0 = add2(pd, qv.x) & AMASK;
            ull t1 = add2(pd, qv.y) & AMASK;
            fma2(acc[u][0], t0, w2);
            fma2(acc[u][1], t1, w2);
        }
    }

    #pragma unroll
    for (int u = 0; u < 4; u++) {
        int i = i0 + ty * 4 + u;
        float si = Ss[ty * 4 + u];
        float2 c0 = unpack2(acc[u][0]);
        float2 c1 = unpack2(acc[u][1]);
        float4 o4;
        o4.x = fast_sigmoid(c0.x + si + Ts[tx * 4 + 0]);
        o4.y = fast_sigmoid(c0.y + si + Ts[tx * 4 + 1]);
        o4.z = fast_sigmoid(c1.x + si + Ts[tx * 4 + 2]);
        o4.w = fast_sigmoid(c1.y + si + Ts[tx * 4 + 3]);
        *(float4*)&out[(size_t)i * NN + j0 + tx * 4] = o4;
    }
}

// ---------------------------------------------------------------------------
extern "C" void kernel_launch(void* const* d_in, const int* in_sizes, int n_in,
                              void* d_out, int out_size)
{
    const float* A_hat = (const float*)d_in[0];
    const float* X     = (const float*)d_in[1];
    const float* eps   = (const float*)d_in[2];
    const float* W1    = (const float*)d_in[3];
    const float* b1    = (const float*)d_in[4];
    const float* Wmu   = (const float*)d_in[5];
    const float* bmu   = (const float*)d_in[6];
    const float* Wlv   = (const float*)d_in[7];
    const float* blv   = (const float*)d_in[8];
    const float* Wd1   = (const float*)d_in[9];
    const float* bd1   = (const float*)d_in[10];
    const float* Wd2   = (const float*)d_in[11];
    const float* bd2   = (const float*)d_in[12];
    float* out = (float*)d_out;

    float* part = nullptr; cudaGetSymbolAddress((void**)&part, g_part);
    __nv_bfloat16* Yhi = nullptr; cudaGetSymbolAddress((void**)&Yhi, g_Yhi);
    __nv_bfloat16* Ylo = nullptr; cudaGetSymbolAddress((void**)&Ylo, g_Ylo);

    // Opt-in to >48KB dynamic smem (no static guard: unconditional, idempotent)
    cudaFuncSetAttribute(wgemm<0>, cudaFuncAttributeMaxDynamicSharedMemorySize, WG_SMEM);
    cudaFuncSetAttribute(wgemm<1>, cudaFuncAttributeMaxDynamicSharedMemorySize, WG_SMEM);

    // K1: part[0..3] = X @ W1^T  (split-K 4, kslice 128)
    wgemm<0><<<dim3(2, 16, 4), 256, WG_SMEM>>>(X, DD, W1, DD, nullptr, nullptr, DD / 4, part);
    // Y(hi/lo) = sum partials, bf16-split
    reduce_split<<<NN * HH / 1024, 256>>>(part);
    // K2: part[0..3] = A_hat @ Y  (split-K 4, kslice 512)
    wgemm<1><<<dim3(2, 16, 4), 256, WG_SMEM>>>(A_hat, NN, nullptr, 0, Yhi, Ylo, NN / 4, part);
    // K3a: streaming reduce + b1 + leaky -> Hh  (MLP 8 per thread)
    k3a_hh<<<NN * HH / 2048, 256>>>(b1);
    // K3b: G = Hh @ [Wmu;Wlv]^T
    k3b_gmat<<<NN / 8, 256>>>(Wmu, Wlv);
    // K4: MLp = A_hat @ G  (split-K 16, 128-row tiles, grid 256)
    k4_ag<<<dim3(NN / 128, 16), 256>>>(A_hat);
    // K5: reduce + biases + mu/logvar + Z + P/Qb + S/T
    k5_epi<<<NN / 8, 256>>>(eps, bmu, blv, Wd1, bd1, Wd2, bd2, out);
    // K6: pairwise decoder
    k6_decoder<<<dim3(NN / 64, NN / 64), 256>>>(out, Wd2);
}